// round 1
// baseline (speedup 1.0000x reference)
#include <cuda_runtime.h>
#include <math.h>

// Problem constants (fixed by the reference)
#define Bv  2
#define Sv  2048
#define Dv  1024
#define Hv  16
#define DHv 64
#define Mv  (Bv * Sv)   // 4096 rows

// Scratch (allocation-free requirement -> __device__ globals)
__device__ float g_q[Mv * Dv];
__device__ float g_k[Mv * Dv];
__device__ float g_v[Mv * Dv];
__device__ float g_ctx[Mv * Dv];

// ---------------------------------------------------------------------------
// SGEMM: C[M,N] = A[M,K] @ B[K,N] (+bias). 64x64 tile, BK=16, 256 thr, 4x4/thr
// ---------------------------------------------------------------------------
template <int M, int N, int K>
__global__ void sgemm_kernel(const float* __restrict__ A,
                             const float* __restrict__ Bm,
                             float* __restrict__ C,
                             const float* __restrict__ bias) {
    constexpr int BM = 64, BN = 64, BK = 16;
    __shared__ float As[BM][BK + 1];   // +1 pad kills store conflicts
    __shared__ float Bs[BK][BN];

    const int tid = threadIdx.x;
    const int tx = tid & 15;
    const int ty = tid >> 4;
    const int m0 = blockIdx.y * BM;
    const int n0 = blockIdx.x * BN;

    float acc[4][4];
#pragma unroll
    for (int i = 0; i < 4; i++)
#pragma unroll
        for (int j = 0; j < 4; j++) acc[i][j] = 0.f;

    for (int k0 = 0; k0 < K; k0 += BK) {
        // A tile: 64x16 = 1024 elems, 4 per thread (coalesced 16-wide rows)
#pragma unroll
        for (int t = 0; t < 4; t++) {
            int idx = tid + t * 256;
            int r = idx >> 4, c = idx & 15;
            As[r][c] = A[(size_t)(m0 + r) * K + k0 + c];
        }
        // B tile: 16x64 = 1024 elems (coalesced 64-wide rows)
#pragma unroll
        for (int t = 0; t < 4; t++) {
            int idx = tid + t * 256;
            int r = idx >> 6, c = idx & 63;
            Bs[r][c] = Bm[(size_t)(k0 + r) * N + n0 + c];
        }
        __syncthreads();

#pragma unroll
        for (int k = 0; k < BK; k++) {
            float a[4], b[4];
#pragma unroll
            for (int i = 0; i < 4; i++) a[i] = As[ty * 4 + i][k];
#pragma unroll
            for (int j = 0; j < 4; j++) b[j] = Bs[k][tx * 4 + j];
#pragma unroll
            for (int i = 0; i < 4; i++)
#pragma unroll
                for (int j = 0; j < 4; j++) acc[i][j] += a[i] * b[j];
        }
        __syncthreads();
    }

#pragma unroll
    for (int i = 0; i < 4; i++) {
        int row = m0 + ty * 4 + i;
#pragma unroll
        for (int j = 0; j < 4; j++) {
            int col = n0 + tx * 4 + j;
            float v = acc[i][j];
            if (bias != nullptr) v += bias[col];
            C[(size_t)row * N + col] = v;
        }
    }
}

// ---------------------------------------------------------------------------
// Flash-style attention.
// Grid: (S/64, H, B). Block: 256 threads. One block = one (b,h) x 64 queries.
// Q pre-scaled by 1/sqrt(D). Mask is [B,1,1,S] -> additive over keys.
// Shared (dynamic): Qs[64][65] | KVs[64][65] (K, then reused for V) |
//                   Ps[64][65] | Ms[64]  = 50176 bytes
// ---------------------------------------------------------------------------
__global__ void attn_kernel(const float* __restrict__ q,
                            const float* __restrict__ k,
                            const float* __restrict__ v,
                            const float* __restrict__ mask,
                            float* __restrict__ ctx) {
    constexpr int TQ = 64, TK = 64, PAD = 65;
    extern __shared__ float sm[];
    float* Qs  = sm;                 // TQ*PAD
    float* KVs = Qs + TQ * PAD;      // TK*PAD
    float* Ps  = KVs + TK * PAD;     // TQ*PAD
    float* Ms  = Ps + TQ * PAD;      // TK

    const int tid = threadIdx.x;
    const int tx = tid & 15;
    const int ty = tid >> 4;
    const int b  = blockIdx.z;
    const int h  = blockIdx.y;
    const int q0 = blockIdx.x * TQ;

    const float scale = 1.0f / 32.0f;  // 1/sqrt(D), D=1024

    // Load + pre-scale Q tile (64x64)
    const float* qbase = q + (size_t)(b * Sv + q0) * Dv + h * DHv;
#pragma unroll
    for (int t = 0; t < 16; t++) {
        int idx = tid + t * 256;
        int r = idx >> 6, c = idx & 63;
        Qs[r * PAD + c] = qbase[(size_t)r * Dv + c] * scale;
    }

    float m_i[4], l_i[4], acc[4][4];
#pragma unroll
    for (int i = 0; i < 4; i++) {
        m_i[i] = -1e30f;
        l_i[i] = 0.f;
#pragma unroll
        for (int j = 0; j < 4; j++) acc[i][j] = 0.f;
    }
    __syncthreads();

    for (int k0 = 0; k0 < Sv; k0 += TK) {
        // Load K tile + mask slice
        const float* kbase = k + (size_t)(b * Sv + k0) * Dv + h * DHv;
#pragma unroll
        for (int t = 0; t < 16; t++) {
            int idx = tid + t * 256;
            int r = idx >> 6, c = idx & 63;
            KVs[r * PAD + c] = kbase[(size_t)r * Dv + c];
        }
        if (tid < TK) Ms[tid] = mask[b * Sv + k0 + tid];
        __syncthreads();

        // Scores: s[i][j] = Qs[ty*4+i][:] . KVs[tx*4+j][:]
        float s[4][4];
#pragma unroll
        for (int i = 0; i < 4; i++)
#pragma unroll
            for (int j = 0; j < 4; j++) s[i][j] = 0.f;

#pragma unroll 8
        for (int d = 0; d < DHv; d++) {
            float a[4], bb[4];
#pragma unroll
            for (int i = 0; i < 4; i++) a[i] = Qs[(ty * 4 + i) * PAD + d];
#pragma unroll
            for (int j = 0; j < 4; j++) bb[j] = KVs[(tx * 4 + j) * PAD + d];
#pragma unroll
            for (int i = 0; i < 4; i++)
#pragma unroll
                for (int j = 0; j < 4; j++) s[i][j] += a[i] * bb[j];
        }
#pragma unroll
        for (int j = 0; j < 4; j++) {
            float mv = Ms[tx * 4 + j];
#pragma unroll
            for (int i = 0; i < 4; i++) s[i][j] += mv;
        }

        // Online softmax per query row (row spread over 16 tx lanes)
#pragma unroll
        for (int i = 0; i < 4; i++) {
            float tm = fmaxf(fmaxf(s[i][0], s[i][1]), fmaxf(s[i][2], s[i][3]));
#pragma unroll
            for (int o = 1; o < 16; o <<= 1)
                tm = fmaxf(tm, __shfl_xor_sync(0xffffffffu, tm, o));
            float newm = fmaxf(m_i[i], tm);
            float corr = __expf(m_i[i] - newm);
            float ps = 0.f;
#pragma unroll
            for (int j = 0; j < 4; j++) {
                float p = __expf(s[i][j] - newm);
                s[i][j] = p;
                ps += p;
            }
#pragma unroll
            for (int o = 1; o < 16; o <<= 1)
                ps += __shfl_xor_sync(0xffffffffu, ps, o);
            l_i[i] = l_i[i] * corr + ps;
            m_i[i] = newm;
#pragma unroll
            for (int j = 0; j < 4; j++) acc[i][j] *= corr;
#pragma unroll
            for (int j = 0; j < 4; j++)
                Ps[(ty * 4 + i) * PAD + tx * 4 + j] = s[i][j];
        }
        __syncthreads();  // Ks reads done, Ps written

        // Load V tile over K's buffer
        const float* vbase = v + (size_t)(b * Sv + k0) * Dv + h * DHv;
#pragma unroll
        for (int t = 0; t < 16; t++) {
            int idx = tid + t * 256;
            int r = idx >> 6, c = idx & 63;
            KVs[r * PAD + c] = vbase[(size_t)r * Dv + c];
        }
        __syncthreads();

        // acc += Ps @ Vs
#pragma unroll 8
        for (int kk = 0; kk < TK; kk++) {
            float p[4], vv[4];
#pragma unroll
            for (int i = 0; i < 4; i++) p[i] = Ps[(ty * 4 + i) * PAD + kk];
#pragma unroll
            for (int j = 0; j < 4; j++) vv[j] = KVs[kk * PAD + tx * 4 + j];
#pragma unroll
            for (int i = 0; i < 4; i++)
#pragma unroll
                for (int j = 0; j < 4; j++) acc[i][j] += p[i] * vv[j];
        }
        __syncthreads();  // before next iteration overwrites KVs/Ps
    }

    // Epilogue: ctx[b, q, h, dh]  (i.e. [B*S, D] row-major)
    float* cbase = ctx + (size_t)(b * Sv + q0) * Dv + h * DHv;
#pragma unroll
    for (int i = 0; i < 4; i++) {
        float inv = 1.0f / l_i[i];
#pragma unroll
        for (int j = 0; j < 4; j++)
            cbase[(size_t)(ty * 4 + i) * Dv + tx * 4 + j] = acc[i][j] * inv;
    }
}

// ---------------------------------------------------------------------------
// Launch
// ---------------------------------------------------------------------------
extern "C" void kernel_launch(void* const* d_in, const int* in_sizes, int n_in,
                              void* d_out, int out_size) {
    const float* x    = (const float*)d_in[0];
    const float* mask = (const float*)d_in[1];
    const float* Wq   = (const float*)d_in[2];
    const float* Wk   = (const float*)d_in[3];
    const float* Wv   = (const float*)d_in[4];
    const float* Wo   = (const float*)d_in[5];
    const float* bo   = (const float*)d_in[6];
    float* out = (float*)d_out;

    float *q_p, *k_p, *v_p, *ctx_p;
    cudaGetSymbolAddress((void**)&q_p,   g_q);
    cudaGetSymbolAddress((void**)&k_p,   g_k);
    cudaGetSymbolAddress((void**)&v_p,   g_v);
    cudaGetSymbolAddress((void**)&ctx_p, g_ctx);

    dim3 gemm_grid(Dv / 64, Mv / 64);  // (16, 64)
    sgemm_kernel<Mv, Dv, Dv><<<gemm_grid, 256>>>(x, Wq, q_p, nullptr);
    sgemm_kernel<Mv, Dv, Dv><<<gemm_grid, 256>>>(x, Wk, k_p, nullptr);
    sgemm_kernel<Mv, Dv, Dv><<<gemm_grid, 256>>>(x, Wv, v_p, nullptr);

    const int smem = (3 * 64 * 65 + 64) * (int)sizeof(float);  // 50176 B
    cudaFuncSetAttribute(attn_kernel,
                         cudaFuncAttributeMaxDynamicSharedMemorySize, smem);
    attn_kernel<<<dim3(Sv / 64, Hv, Bv), 256, smem>>>(q_p, k_p, v_p, mask, ctx_p);

    sgemm_kernel<Mv, Dv, Dv><<<gemm_grid, 256>>>(ctx_p, Wo, out, bo);
}

// round 3
// speedup vs baseline: 1.5336x; 1.5336x over previous
#include <cuda_runtime.h>
#include <cstdint>
#include <math.h>

// Problem constants
#define Bv  2
#define Sv  2048
#define Dv  1024
#define Hv  16
#define DHv 64
#define Mv  (Bv * Sv)   // 4096

// Scratch (__device__ globals: allocation-free rule)
__device__ float g_q[Mv * Dv];
__device__ float g_k[Mv * Dv];
__device__ float g_v[Mv * Dv];
__device__ float g_ctx[Mv * Dv];

// ---------------------------------------------------------------------------
// Helpers (arch-generic PTX only: mma.sync tf32 + cp.async; NO tcgen05)
// ---------------------------------------------------------------------------
__device__ __forceinline__ uint32_t smem_u32(const void* p) {
    uint32_t a;
    asm("{ .reg .u64 t; cvta.to.shared.u64 t, %1; cvt.u32.u64 %0, t; }" : "=r"(a) : "l"(p));
    return a;
}
__device__ __forceinline__ uint32_t f2tf(float x) {
    uint32_t r;
    asm("cvt.rna.tf32.f32 %0, %1;" : "=r"(r) : "f"(x));
    return r;
}
#define CP16(dst, src) \
    asm volatile("cp.async.cg.shared.global [%0], [%1], 16;" :: "r"(dst), "l"(src))
#define CP_COMMIT() asm volatile("cp.async.commit_group;" ::: "memory")
#define CP_WAIT1()  asm volatile("cp.async.wait_group 1;" ::: "memory")

__device__ __forceinline__ void mma_tf32(float c[4], const uint32_t a[4],
                                         const uint32_t b[2]) {
    asm volatile(
        "mma.sync.aligned.m16n8k8.row.col.f32.tf32.tf32.f32 "
        "{%0,%1,%2,%3}, {%4,%5,%6,%7}, {%8,%9}, {%0,%1,%2,%3};"
        : "+f"(c[0]), "+f"(c[1]), "+f"(c[2]), "+f"(c[3])
        : "r"(a[0]), "r"(a[1]), "r"(a[2]), "r"(a[3]), "r"(b[0]), "r"(b[1]));
}

// ---------------------------------------------------------------------------
// tf32 mma.sync GEMM: C[4096,1024] = A[4096,1024] @ W[1024,1024] (+bias)
// CTA tile 128x128, BK=32, 256 threads (8 warps, 2x4 -> 64x32 warp tiles).
// Double-buffered SMEM via cp.async. A stride 36 fl, B stride 136 fl (pads
// make all fragment LDS bank-conflict-free). grid.z batches QKV.
// ---------------------------------------------------------------------------
#define A_STRIDE 36     // 32 + 4 pad
#define B_STRIDE 136    // 128 + 8 pad
#define A_TILE_F (128 * A_STRIDE)   // 4608 floats
#define B_TILE_F (32 * B_STRIDE)    // 4352 floats
#define GEMM_SMEM ((2 * A_TILE_F + 2 * B_TILE_F) * 4)   // 71680 B

__global__ __launch_bounds__(256)
void tf32_mma_gemm(const float* __restrict__ A,
                   const float* __restrict__ w0, const float* __restrict__ w1,
                   const float* __restrict__ w2,
                   float* __restrict__ c0, float* __restrict__ c1,
                   float* __restrict__ c2,
                   const float* __restrict__ bias) {
    extern __shared__ float smf[];
    float* Asb[2] = {smf, smf + A_TILE_F};
    float* Bsb[2] = {smf + 2 * A_TILE_F, smf + 2 * A_TILE_F + B_TILE_F};

    const int tid  = threadIdx.x;
    const int wid  = tid >> 5;
    const int lane = tid & 31;
    const int g = lane >> 2;   // group 0..7
    const int t = lane & 3;    // thread-in-group 0..3

    const float* W = (blockIdx.z == 0) ? w0 : (blockIdx.z == 1) ? w1 : w2;
    float* C = (blockIdx.z == 0) ? c0 : (blockIdx.z == 1) ? c1 : c2;

    const int n0 = blockIdx.x * 128;
    const int m0 = blockIdx.y * 128;
    const int warp_m0 = (wid >> 2) * 64;   // 0 or 64
    const int warp_n0 = (wid & 3) * 32;    // 0..96

    float acc[4][4][4];
#pragma unroll
    for (int mt = 0; mt < 4; mt++)
#pragma unroll
        for (int nt = 0; nt < 4; nt++)
#pragma unroll
            for (int e = 0; e < 4; e++) acc[mt][nt][e] = 0.f;

    // Prefetch chunk c into buffer buf
    auto prefetch = [&](int chunk, int buf) {
        const int k0 = chunk * 32;
        const uint32_t as = smem_u32(Asb[buf]);
        const uint32_t bs = smem_u32(Bsb[buf]);
        const float* Ag = A + (size_t)m0 * Dv + k0;
        const float* Bg = W + (size_t)k0 * Dv + n0;
#pragma unroll
        for (int it = 0; it < 4; it++) {
            int idx = it * 256 + tid;
            int r = idx >> 3, c4 = idx & 7;   // A: 8 float4 per row
            CP16(as + (uint32_t)(r * A_STRIDE + c4 * 4) * 4,
                 Ag + (size_t)r * Dv + c4 * 4);
        }
#pragma unroll
        for (int it = 0; it < 4; it++) {
            int idx = it * 256 + tid;
            int r = idx >> 5, c4 = idx & 31;  // B: 32 float4 per row
            CP16(bs + (uint32_t)(r * B_STRIDE + c4 * 4) * 4,
                 Bg + (size_t)r * Dv + c4 * 4);
        }
    };

    prefetch(0, 0); CP_COMMIT();
    prefetch(1, 1); CP_COMMIT();

    for (int chunk = 0; chunk < Dv / 32; chunk++) {
        const int buf = chunk & 1;
        CP_WAIT1();
        __syncthreads();

        const float* As = Asb[buf];
        const float* Bs = Bsb[buf];
#pragma unroll
        for (int ks = 0; ks < 4; ks++) {
            const int kk = ks * 8;
            uint32_t af[4][4];
#pragma unroll
            for (int mt = 0; mt < 4; mt++) {
                const float* p = As + (warp_m0 + mt * 16 + g) * A_STRIDE + kk + t;
                af[mt][0] = f2tf(p[0]);
                af[mt][1] = f2tf(p[8 * A_STRIDE]);
                af[mt][2] = f2tf(p[4]);
                af[mt][3] = f2tf(p[8 * A_STRIDE + 4]);
            }
            uint32_t bf[4][2];
#pragma unroll
            for (int nt = 0; nt < 4; nt++) {
                const float* p = Bs + (kk + t) * B_STRIDE + warp_n0 + nt * 8 + g;
                bf[nt][0] = f2tf(p[0]);
                bf[nt][1] = f2tf(p[4 * B_STRIDE]);
            }
#pragma unroll
            for (int mt = 0; mt < 4; mt++)
#pragma unroll
                for (int nt = 0; nt < 4; nt++)
                    mma_tf32(acc[mt][nt], af[mt], bf[nt]);
        }
        __syncthreads();

        if (chunk + 2 < Dv / 32) prefetch(chunk + 2, buf);
        CP_COMMIT();   // empty groups at the tail keep the count consistent
    }

    // Epilogue: fragment layout c0/c1 at (row g, col 2t/(2t+1)), c2/c3 at row g+8
#pragma unroll
    for (int mt = 0; mt < 4; mt++) {
        const int rm = m0 + warp_m0 + mt * 16 + g;
#pragma unroll
        for (int nt = 0; nt < 4; nt++) {
            const int cn = n0 + warp_n0 + nt * 8 + t * 2;
            float b0 = 0.f, b1 = 0.f;
            if (bias != nullptr) { b0 = bias[cn]; b1 = bias[cn + 1]; }
            float2 v0 = make_float2(acc[mt][nt][0] + b0, acc[mt][nt][1] + b1);
            float2 v1 = make_float2(acc[mt][nt][2] + b0, acc[mt][nt][3] + b1);
            *(float2*)(C + (size_t)rm * Dv + cn) = v0;
            *(float2*)(C + (size_t)(rm + 8) * Dv + cn) = v1;
        }
    }
}

// ---------------------------------------------------------------------------
// Flash-style fp32 attention (unchanged, known-good)
// ---------------------------------------------------------------------------
__global__ void attn_kernel(const float* __restrict__ q,
                            const float* __restrict__ k,
                            const float* __restrict__ v,
                            const float* __restrict__ mask,
                            float* __restrict__ ctx) {
    constexpr int TQ = 64, TK = 64, PAD = 65;
    extern __shared__ float smf[];
    float* Qs  = smf;
    float* KVs = Qs + TQ * PAD;
    float* Ps  = KVs + TK * PAD;
    float* Ms  = Ps + TQ * PAD;

    const int tid = threadIdx.x;
    const int tx = tid & 15;
    const int ty = tid >> 4;
    const int b  = blockIdx.z;
    const int h  = blockIdx.y;
    const int q0 = blockIdx.x * TQ;

    const float scale = 1.0f / 32.0f;

    const float* qbase = q + (size_t)(b * Sv + q0) * Dv + h * DHv;
#pragma unroll
    for (int t = 0; t < 16; t++) {
        int idx = tid + t * 256;
        int r = idx >> 6, c = idx & 63;
        Qs[r * PAD + c] = qbase[(size_t)r * Dv + c] * scale;
    }

    float m_i[4], l_i[4], acc[4][4];
#pragma unroll
    for (int i = 0; i < 4; i++) {
        m_i[i] = -1e30f;
        l_i[i] = 0.f;
#pragma unroll
        for (int j = 0; j < 4; j++) acc[i][j] = 0.f;
    }
    __syncthreads();

    for (int k0 = 0; k0 < Sv; k0 += TK) {
        const float* kbase = k + (size_t)(b * Sv + k0) * Dv + h * DHv;
#pragma unroll
        for (int t = 0; t < 16; t++) {
            int idx = tid + t * 256;
            int r = idx >> 6, c = idx & 63;
            KVs[r * PAD + c] = kbase[(size_t)r * Dv + c];
        }
        if (tid < TK) Ms[tid] = mask[b * Sv + k0 + tid];
        __syncthreads();

        float s[4][4];
#pragma unroll
        for (int i = 0; i < 4; i++)
#pragma unroll
            for (int j = 0; j < 4; j++) s[i][j] = 0.f;

#pragma unroll 8
        for (int d = 0; d < DHv; d++) {
            float a[4], bb[4];
#pragma unroll
            for (int i = 0; i < 4; i++) a[i] = Qs[(ty * 4 + i) * PAD + d];
#pragma unroll
            for (int j = 0; j < 4; j++) bb[j] = KVs[(tx * 4 + j) * PAD + d];
#pragma unroll
            for (int i = 0; i < 4; i++)
#pragma unroll
                for (int j = 0; j < 4; j++) s[i][j] += a[i] * bb[j];
        }
#pragma unroll
        for (int j = 0; j < 4; j++) {
            float mv = Ms[tx * 4 + j];
#pragma unroll
            for (int i = 0; i < 4; i++) s[i][j] += mv;
        }

#pragma unroll
        for (int i = 0; i < 4; i++) {
            float tm = fmaxf(fmaxf(s[i][0], s[i][1]), fmaxf(s[i][2], s[i][3]));
#pragma unroll
            for (int o = 1; o < 16; o <<= 1)
                tm = fmaxf(tm, __shfl_xor_sync(0xffffffffu, tm, o));
            float newm = fmaxf(m_i[i], tm);
            float corr = __expf(m_i[i] - newm);
            float ps = 0.f;
#pragma unroll
            for (int j = 0; j < 4; j++) {
                float p = __expf(s[i][j] - newm);
                s[i][j] = p;
                ps += p;
            }
#pragma unroll
            for (int o = 1; o < 16; o <<= 1)
                ps += __shfl_xor_sync(0xffffffffu, ps, o);
            l_i[i] = l_i[i] * corr + ps;
            m_i[i] = newm;
#pragma unroll
            for (int j = 0; j < 4; j++) acc[i][j] *= corr;
#pragma unroll
            for (int j = 0; j < 4; j++)
                Ps[(ty * 4 + i) * PAD + tx * 4 + j] = s[i][j];
        }
        __syncthreads();

        const float* vbase = v + (size_t)(b * Sv + k0) * Dv + h * DHv;
#pragma unroll
        for (int t = 0; t < 16; t++) {
            int idx = tid + t * 256;
            int r = idx >> 6, c = idx & 63;
            KVs[r * PAD + c] = vbase[(size_t)r * Dv + c];
        }
        __syncthreads();

#pragma unroll 8
        for (int kk = 0; kk < TK; kk++) {
            float p[4], vv[4];
#pragma unroll
            for (int i = 0; i < 4; i++) p[i] = Ps[(ty * 4 + i) * PAD + kk];
#pragma unroll
            for (int j = 0; j < 4; j++) vv[j] = KVs[kk * PAD + tx * 4 + j];
#pragma unroll
            for (int i = 0; i < 4; i++)
#pragma unroll
                for (int j = 0; j < 4; j++) acc[i][j] += p[i] * vv[j];
        }
        __syncthreads();
    }

    float* cbase = ctx + (size_t)(b * Sv + q0) * Dv + h * DHv;
#pragma unroll
    for (int i = 0; i < 4; i++) {
        float inv = 1.0f / l_i[i];
#pragma unroll
        for (int j = 0; j < 4; j++)
            cbase[(size_t)(ty * 4 + i) * Dv + tx * 4 + j] = acc[i][j] * inv;
    }
}

// ---------------------------------------------------------------------------
// Launch
// ---------------------------------------------------------------------------
extern "C" void kernel_launch(void* const* d_in, const int* in_sizes, int n_in,
                              void* d_out, int out_size) {
    const float* x    = (const float*)d_in[0];
    const float* mask = (const float*)d_in[1];
    const float* Wq   = (const float*)d_in[2];
    const float* Wk   = (const float*)d_in[3];
    const float* Wv   = (const float*)d_in[4];
    const float* Wo   = (const float*)d_in[5];
    const float* bo   = (const float*)d_in[6];
    float* out = (float*)d_out;

    float *q_p, *k_p, *v_p, *ctx_p;
    cudaGetSymbolAddress((void**)&q_p,   g_q);
    cudaGetSymbolAddress((void**)&k_p,   g_k);
    cudaGetSymbolAddress((void**)&v_p,   g_v);
    cudaGetSymbolAddress((void**)&ctx_p, g_ctx);

    cudaFuncSetAttribute(tf32_mma_gemm,
                         cudaFuncAttributeMaxDynamicSharedMemorySize, GEMM_SMEM);

    // Fused QKV projections (grid.z selects weight/output)
    tf32_mma_gemm<<<dim3(Dv / 128, Mv / 128, 3), 256, GEMM_SMEM>>>(
        x, Wq, Wk, Wv, q_p, k_p, v_p, nullptr);

    const int attn_smem = (3 * 64 * 65 + 64) * (int)sizeof(float);
    cudaFuncSetAttribute(attn_kernel,
                         cudaFuncAttributeMaxDynamicSharedMemorySize, attn_smem);
    attn_kernel<<<dim3(Sv / 64, Hv, Bv), 256, attn_smem>>>(q_p, k_p, v_p, mask, ctx_p);

    // Output projection with bias
    tf32_mma_gemm<<<dim3(Dv / 128, Mv / 128, 1), 256, GEMM_SMEM>>>(
        ctx_p, Wo, Wo, Wo, out, out, out, bo);
}

// round 4
// speedup vs baseline: 3.6720x; 2.3943x over previous
#include <cuda_runtime.h>
#include <cstdint>
#include <math.h>

// Problem constants
#define Bv  2
#define Sv  2048
#define Dv  1024
#define Hv  16
#define DHv 64
#define Mv  (Bv * Sv)   // 4096

// Scratch
__device__ float g_q[Mv * Dv];
__device__ float g_k[Mv * Dv];
__device__ float g_v[Mv * Dv];
__device__ float g_ctx[Mv * Dv];

// ---------------------------------------------------------------------------
// Helpers (arch-generic PTX: mma.sync tf32 + cp.async)
// ---------------------------------------------------------------------------
__device__ __forceinline__ uint32_t smem_u32(const void* p) {
    uint32_t a;
    asm("{ .reg .u64 t; cvta.to.shared.u64 t, %1; cvt.u32.u64 %0, t; }" : "=r"(a) : "l"(p));
    return a;
}
__device__ __forceinline__ uint32_t f2tf(float x) {
    uint32_t r;
    asm("cvt.rna.tf32.f32 %0, %1;" : "=r"(r) : "f"(x));
    return r;
}
#define CP16(dst, src) \
    asm volatile("cp.async.cg.shared.global [%0], [%1], 16;" :: "r"(dst), "l"(src))
#define CP_COMMIT() asm volatile("cp.async.commit_group;" ::: "memory")
#define CP_WAIT1()  asm volatile("cp.async.wait_group 1;" ::: "memory")

__device__ __forceinline__ void mma_tf32(float c[4], const uint32_t a[4],
                                         const uint32_t b[2]) {
    asm volatile(
        "mma.sync.aligned.m16n8k8.row.col.f32.tf32.tf32.f32 "
        "{%0,%1,%2,%3}, {%4,%5,%6,%7}, {%8,%9}, {%0,%1,%2,%3};"
        : "+f"(c[0]), "+f"(c[1]), "+f"(c[2]), "+f"(c[3])
        : "r"(a[0]), "r"(a[1]), "r"(a[2]), "r"(a[3]), "r"(b[0]), "r"(b[1]));
}

// ---------------------------------------------------------------------------
// tf32 mma GEMM (round-3, + occupancy 2)
// ---------------------------------------------------------------------------
#define A_STRIDE 36
#define B_STRIDE 136
#define A_TILE_F (128 * A_STRIDE)
#define B_TILE_F (32 * B_STRIDE)
#define GEMM_SMEM ((2 * A_TILE_F + 2 * B_TILE_F) * 4)

__global__ __launch_bounds__(256, 2)
void tf32_mma_gemm(const float* __restrict__ A,
                   const float* __restrict__ w0, const float* __restrict__ w1,
                   const float* __restrict__ w2,
                   float* __restrict__ c0, float* __restrict__ c1,
                   float* __restrict__ c2,
                   const float* __restrict__ bias) {
    extern __shared__ float smf[];
    float* Asb[2] = {smf, smf + A_TILE_F};
    float* Bsb[2] = {smf + 2 * A_TILE_F, smf + 2 * A_TILE_F + B_TILE_F};

    const int tid  = threadIdx.x;
    const int wid  = tid >> 5;
    const int lane = tid & 31;
    const int g = lane >> 2;
    const int t = lane & 3;

    const float* W = (blockIdx.z == 0) ? w0 : (blockIdx.z == 1) ? w1 : w2;
    float* C = (blockIdx.z == 0) ? c0 : (blockIdx.z == 1) ? c1 : c2;

    const int n0 = blockIdx.x * 128;
    const int m0 = blockIdx.y * 128;
    const int warp_m0 = (wid >> 2) * 64;
    const int warp_n0 = (wid & 3) * 32;

    float acc[4][4][4];
#pragma unroll
    for (int mt = 0; mt < 4; mt++)
#pragma unroll
        for (int nt = 0; nt < 4; nt++)
#pragma unroll
            for (int e = 0; e < 4; e++) acc[mt][nt][e] = 0.f;

    auto prefetch = [&](int chunk, int buf) {
        const int k0 = chunk * 32;
        const uint32_t as = smem_u32(Asb[buf]);
        const uint32_t bs = smem_u32(Bsb[buf]);
        const float* Ag = A + (size_t)m0 * Dv + k0;
        const float* Bg = W + (size_t)k0 * Dv + n0;
#pragma unroll
        for (int it = 0; it < 4; it++) {
            int idx = it * 256 + tid;
            int r = idx >> 3, c4 = idx & 7;
            CP16(as + (uint32_t)(r * A_STRIDE + c4 * 4) * 4,
                 Ag + (size_t)r * Dv + c4 * 4);
        }
#pragma unroll
        for (int it = 0; it < 4; it++) {
            int idx = it * 256 + tid;
            int r = idx >> 5, c4 = idx & 31;
            CP16(bs + (uint32_t)(r * B_STRIDE + c4 * 4) * 4,
                 Bg + (size_t)r * Dv + c4 * 4);
        }
    };

    prefetch(0, 0); CP_COMMIT();
    prefetch(1, 1); CP_COMMIT();

    for (int chunk = 0; chunk < Dv / 32; chunk++) {
        const int buf = chunk & 1;
        CP_WAIT1();
        __syncthreads();

        const float* As = Asb[buf];
        const float* Bs = Bsb[buf];
#pragma unroll
        for (int ks = 0; ks < 4; ks++) {
            const int kk = ks * 8;
            uint32_t af[4][4];
#pragma unroll
            for (int mt = 0; mt < 4; mt++) {
                const float* p = As + (warp_m0 + mt * 16 + g) * A_STRIDE + kk + t;
                af[mt][0] = f2tf(p[0]);
                af[mt][1] = f2tf(p[8 * A_STRIDE]);
                af[mt][2] = f2tf(p[4]);
                af[mt][3] = f2tf(p[8 * A_STRIDE + 4]);
            }
            uint32_t bf[4][2];
#pragma unroll
            for (int nt = 0; nt < 4; nt++) {
                const float* p = Bs + (kk + t) * B_STRIDE + warp_n0 + nt * 8 + g;
                bf[nt][0] = f2tf(p[0]);
                bf[nt][1] = f2tf(p[4 * B_STRIDE]);
            }
#pragma unroll
            for (int mt = 0; mt < 4; mt++)
#pragma unroll
                for (int nt = 0; nt < 4; nt++)
                    mma_tf32(acc[mt][nt], af[mt], bf[nt]);
        }
        __syncthreads();

        if (chunk + 2 < Dv / 32) prefetch(chunk + 2, buf);
        CP_COMMIT();
    }

#pragma unroll
    for (int mt = 0; mt < 4; mt++) {
        const int rm = m0 + warp_m0 + mt * 16 + g;
#pragma unroll
        for (int nt = 0; nt < 4; nt++) {
            const int cn = n0 + warp_n0 + nt * 8 + t * 2;
            float b0 = 0.f, b1 = 0.f;
            if (bias != nullptr) { b0 = bias[cn]; b1 = bias[cn + 1]; }
            float2 v0 = make_float2(acc[mt][nt][0] + b0, acc[mt][nt][1] + b1);
            float2 v1 = make_float2(acc[mt][nt][2] + b0, acc[mt][nt][3] + b1);
            *(float2*)(C + (size_t)rm * Dv + cn) = v0;
            *(float2*)(C + (size_t)(rm + 8) * Dv + cn) = v1;
        }
    }
}

// ---------------------------------------------------------------------------
// tf32 mma flash attention.
// Grid (S/128, H, B), 256 threads = 8 warps; warp w owns queries w*16..w*16+15.
// K/V tiles of 64 keys, double-buffered cp.async. Softmax warp-local.
// SMEM strides: K 68 (B-frag 4g+t), V 72 (B-frag 8t+g), P/Q 68 (A-frag 4g+t)
// -> all fragment LDS conflict-free.
// ---------------------------------------------------------------------------
#define KSTR 68
#define VSTR 72
#define PSTR 68
#define OFF_K 0                        // 2 bufs x 64*68
#define OFF_V (2 * 64 * KSTR)          // 8704
#define OFF_P (OFF_V + 2 * 64 * VSTR)  // 17920
#define OFF_M (OFF_P + 128 * PSTR)     // 26624
#define ATTN_SMEM ((OFF_M + 2 * 64) * 4)   // 107008 B

__global__ __launch_bounds__(256, 2)
void attn_mma(const float* __restrict__ q,
              const float* __restrict__ k,
              const float* __restrict__ v,
              const float* __restrict__ mask,
              float* __restrict__ ctx) {
    extern __shared__ float smf[];
    float* KsB = smf + OFF_K;
    float* VsB = smf + OFF_V;
    float* Ps  = smf + OFF_P;
    float* MkB = smf + OFF_M;

    const int tid  = threadIdx.x;
    const int wid  = tid >> 5;
    const int lane = tid & 31;
    const int g = lane >> 2;
    const int t = lane & 3;
    const int b  = blockIdx.z;
    const int h  = blockIdx.y;
    const int q0 = blockIdx.x * 128;
    const int row0 = wid * 16;
    const float scale = 1.0f / 32.0f;   // 1/sqrt(D)

    // Prefetch K/V/mask for tiles 0 and 1
    auto prefetch = [&](int it) {
        const int buf = it & 1;
        const int k0 = it * 64;
        const uint32_t ks = smem_u32(KsB + buf * 64 * KSTR);
        const uint32_t vs = smem_u32(VsB + buf * 64 * VSTR);
        const float* kg = k + (size_t)(b * Sv + k0) * Dv + h * DHv;
        const float* vg = v + (size_t)(b * Sv + k0) * Dv + h * DHv;
#pragma unroll
        for (int p = 0; p < 4; p++) {
            int idx = p * 256 + tid;
            int r = idx >> 4, c4 = idx & 15;
            CP16(ks + (uint32_t)(r * KSTR + c4 * 4) * 4, kg + (size_t)r * Dv + c4 * 4);
        }
#pragma unroll
        for (int p = 0; p < 4; p++) {
            int idx = p * 256 + tid;
            int r = idx >> 4, c4 = idx & 15;
            CP16(vs + (uint32_t)(r * VSTR + c4 * 4) * 4, vg + (size_t)r * Dv + c4 * 4);
        }
        if (tid < 16)
            CP16(smem_u32(MkB + buf * 64 + tid * 4), mask + b * Sv + k0 + tid * 4);
    };

    prefetch(0); CP_COMMIT();
    prefetch(1); CP_COMMIT();

    // Stage Q tile into Ps area, extract A-fragments to registers (scaled)
    {
        const float* qg = q + (size_t)(b * Sv + q0) * Dv + h * DHv;
#pragma unroll
        for (int p = 0; p < 8; p++) {
            int idx = p * 256 + tid;
            int r = idx >> 4, c4 = idx & 15;
            *(float4*)(Ps + r * PSTR + c4 * 4) =
                *(const float4*)(qg + (size_t)r * Dv + c4 * 4);
        }
    }
    __syncthreads();

    uint32_t qf[8][4];
#pragma unroll
    for (int kk = 0; kk < 8; kk++) {
        const float* p0 = Ps + (row0 + g) * PSTR + kk * 8 + t;
        const float* p1 = Ps + (row0 + 8 + g) * PSTR + kk * 8 + t;
        qf[kk][0] = f2tf(p0[0] * scale);
        qf[kk][1] = f2tf(p1[0] * scale);
        qf[kk][2] = f2tf(p0[4] * scale);
        qf[kk][3] = f2tf(p1[4] * scale);
    }
    __syncthreads();   // Ps now free for P tiles

    float m_lo = -1e30f, m_hi = -1e30f, l_lo = 0.f, l_hi = 0.f;
    float acc[8][4];
#pragma unroll
    for (int nt = 0; nt < 8; nt++)
#pragma unroll
        for (int e = 0; e < 4; e++) acc[nt][e] = 0.f;

    float* PsW = Ps + row0 * PSTR;   // warp-private P strip

    for (int it = 0; it < Sv / 64; it++) {
        const int buf = it & 1;
        const float* Ks = KsB + buf * 64 * KSTR;
        const float* Vs = VsB + buf * 64 * VSTR;
        const float* Mk = MkB + buf * 64;

        CP_WAIT1();
        __syncthreads();

        // --- S = Q @ K^T (B-side: raw fp32 bits -> HW tf32 truncation) ---
        float s[8][4];
#pragma unroll
        for (int nt = 0; nt < 8; nt++)
#pragma unroll
            for (int e = 0; e < 4; e++) s[nt][e] = 0.f;

#pragma unroll
        for (int kk = 0; kk < 8; kk++) {
            uint32_t bf[8][2];
#pragma unroll
            for (int nt = 0; nt < 8; nt++) {
                const float* p = Ks + (nt * 8 + g) * KSTR + kk * 8 + t;
                bf[nt][0] = __float_as_uint(p[0]);
                bf[nt][1] = __float_as_uint(p[4]);
            }
#pragma unroll
            for (int nt = 0; nt < 8; nt++)
                mma_tf32(s[nt], qf[kk], bf[nt]);
        }

        // --- mask + online softmax (warp-local; quad lanes share a row) ---
        float tmax_lo = -1e30f, tmax_hi = -1e30f;
#pragma unroll
        for (int nt = 0; nt < 8; nt++) {
            float mv0 = Mk[nt * 8 + 2 * t];
            float mv1 = Mk[nt * 8 + 2 * t + 1];
            s[nt][0] += mv0; s[nt][1] += mv1;
            s[nt][2] += mv0; s[nt][3] += mv1;
            tmax_lo = fmaxf(tmax_lo, fmaxf(s[nt][0], s[nt][1]));
            tmax_hi = fmaxf(tmax_hi, fmaxf(s[nt][2], s[nt][3]));
        }
#pragma unroll
        for (int o = 1; o < 4; o <<= 1) {
            tmax_lo = fmaxf(tmax_lo, __shfl_xor_sync(0xffffffffu, tmax_lo, o));
            tmax_hi = fmaxf(tmax_hi, __shfl_xor_sync(0xffffffffu, tmax_hi, o));
        }
        float nm_lo = fmaxf(m_lo, tmax_lo);
        float nm_hi = fmaxf(m_hi, tmax_hi);
        float cr_lo = __expf(m_lo - nm_lo);
        float cr_hi = __expf(m_hi - nm_hi);
        m_lo = nm_lo; m_hi = nm_hi;

        float sum_lo = 0.f, sum_hi = 0.f;
#pragma unroll
        for (int nt = 0; nt < 8; nt++) {
            s[nt][0] = __expf(s[nt][0] - nm_lo);
            s[nt][1] = __expf(s[nt][1] - nm_lo);
            s[nt][2] = __expf(s[nt][2] - nm_hi);
            s[nt][3] = __expf(s[nt][3] - nm_hi);
            sum_lo += s[nt][0] + s[nt][1];
            sum_hi += s[nt][2] + s[nt][3];
        }
#pragma unroll
        for (int o = 1; o < 4; o <<= 1) {
            sum_lo += __shfl_xor_sync(0xffffffffu, sum_lo, o);
            sum_hi += __shfl_xor_sync(0xffffffffu, sum_hi, o);
        }
        l_lo = l_lo * cr_lo + sum_lo;
        l_hi = l_hi * cr_hi + sum_hi;

#pragma unroll
        for (int nt = 0; nt < 8; nt++) {
            acc[nt][0] *= cr_lo; acc[nt][1] *= cr_lo;
            acc[nt][2] *= cr_hi; acc[nt][3] *= cr_hi;
            *(float2*)(PsW + g * PSTR + nt * 8 + 2 * t) =
                make_float2(s[nt][0], s[nt][1]);
            *(float2*)(PsW + (g + 8) * PSTR + nt * 8 + 2 * t) =
                make_float2(s[nt][2], s[nt][3]);
        }
        __syncwarp();

        // --- acc += P @ V ---
#pragma unroll
        for (int kk = 0; kk < 8; kk++) {
            uint32_t af[4];
            af[0] = f2tf(PsW[g * PSTR + kk * 8 + t]);
            af[1] = f2tf(PsW[(g + 8) * PSTR + kk * 8 + t]);
            af[2] = f2tf(PsW[g * PSTR + kk * 8 + t + 4]);
            af[3] = f2tf(PsW[(g + 8) * PSTR + kk * 8 + t + 4]);
#pragma unroll
            for (int nt = 0; nt < 8; nt++) {
                uint32_t bf[2];
                bf[0] = __float_as_uint(Vs[(kk * 8 + t) * VSTR + nt * 8 + g]);
                bf[1] = __float_as_uint(Vs[(kk * 8 + t + 4) * VSTR + nt * 8 + g]);
                mma_tf32(acc[nt], af, bf);
            }
        }
        __syncthreads();   // all warps done reading buf before overwrite

        if (it + 2 < Sv / 64) prefetch(it + 2);
        CP_COMMIT();
    }

    // Epilogue
    const float inv_lo = 1.0f / l_lo;
    const float inv_hi = 1.0f / l_hi;
    float* c0 = ctx + (size_t)(b * Sv + q0 + row0 + g) * Dv + h * DHv;
    float* c1 = ctx + (size_t)(b * Sv + q0 + row0 + 8 + g) * Dv + h * DHv;
#pragma unroll
    for (int nt = 0; nt < 8; nt++) {
        int cn = nt * 8 + 2 * t;
        *(float2*)(c0 + cn) = make_float2(acc[nt][0] * inv_lo, acc[nt][1] * inv_lo);
        *(float2*)(c1 + cn) = make_float2(acc[nt][2] * inv_hi, acc[nt][3] * inv_hi);
    }
}

// ---------------------------------------------------------------------------
// Launch
// ---------------------------------------------------------------------------
extern "C" void kernel_launch(void* const* d_in, const int* in_sizes, int n_in,
                              void* d_out, int out_size) {
    const float* x    = (const float*)d_in[0];
    const float* mask = (const float*)d_in[1];
    const float* Wq   = (const float*)d_in[2];
    const float* Wk   = (const float*)d_in[3];
    const float* Wv   = (const float*)d_in[4];
    const float* Wo   = (const float*)d_in[5];
    const float* bo   = (const float*)d_in[6];
    float* out = (float*)d_out;

    float *q_p, *k_p, *v_p, *ctx_p;
    cudaGetSymbolAddress((void**)&q_p,   g_q);
    cudaGetSymbolAddress((void**)&k_p,   g_k);
    cudaGetSymbolAddress((void**)&v_p,   g_v);
    cudaGetSymbolAddress((void**)&ctx_p, g_ctx);

    cudaFuncSetAttribute(tf32_mma_gemm,
                         cudaFuncAttributeMaxDynamicSharedMemorySize, GEMM_SMEM);
    cudaFuncSetAttribute(attn_mma,
                         cudaFuncAttributeMaxDynamicSharedMemorySize, ATTN_SMEM);

    tf32_mma_gemm<<<dim3(Dv / 128, Mv / 128, 3), 256, GEMM_SMEM>>>(
        x, Wq, Wk, Wv, q_p, k_p, v_p, nullptr);

    attn_mma<<<dim3(Sv / 128, Hv, Bv), 256, ATTN_SMEM>>>(
        q_p, k_p, v_p, mask, ctx_p);

    tf32_mma_gemm<<<dim3(Dv / 128, Mv / 128, 1), 256, GEMM_SMEM>>>(
        ctx_p, Wo, Wo, Wo, out, out, out, bo);
}

// round 5
// speedup vs baseline: 6.4427x; 1.7545x over previous
#include <cuda_runtime.h>
#include <cuda_fp16.h>
#include <cstdint>
#include <math.h>

// Problem constants
#define Bv  2
#define Sv  2048
#define Dv  1024
#define Hv  16
#define DHv 64
#define Mv  (Bv * Sv)   // 4096

#define LOG2E 1.4426950408889634f

// Scratch (__device__ globals)
__device__ __half g_xh[Mv * Dv];
__device__ __half g_qh[Mv * Dv];
__device__ __half g_kh[Mv * Dv];
__device__ __half g_vt[Dv * Mv];      // V transposed: [d][token]
__device__ __half g_ctxh[Mv * Dv];
__device__ __half g_wqt[Dv * Dv];     // W transposed fp16: [n][k]
__device__ __half g_wkt[Dv * Dv];
__device__ __half g_wvt[Dv * Dv];
__device__ __half g_wot[Dv * Dv];

// ---------------------------------------------------------------------------
// Helpers (arch-generic PTX: mma.sync f16 + cp.async)
// ---------------------------------------------------------------------------
__device__ __forceinline__ uint32_t smem_u32(const void* p) {
    uint32_t a;
    asm("{ .reg .u64 t; cvta.to.shared.u64 t, %1; cvt.u32.u64 %0, t; }" : "=r"(a) : "l"(p));
    return a;
}
#define CP16(dst, src) \
    asm volatile("cp.async.cg.shared.global [%0], [%1], 16;" :: "r"(dst), "l"(src))
#define CP_COMMIT() asm volatile("cp.async.commit_group;" ::: "memory")
#define CP_WAIT1()  asm volatile("cp.async.wait_group 1;" ::: "memory")

__device__ __forceinline__ float ex2f(float x) {
    float r;
    asm("ex2.approx.f32 %0, %1;" : "=f"(r) : "f"(x));
    return r;
}
__device__ __forceinline__ void mma_f16(float c[4], const uint32_t a[4],
                                        const uint32_t b[2]) {
    asm volatile(
        "mma.sync.aligned.m16n8k16.row.col.f32.f16.f16.f32 "
        "{%0,%1,%2,%3}, {%4,%5,%6,%7}, {%8,%9}, {%0,%1,%2,%3};"
        : "+f"(c[0]), "+f"(c[1]), "+f"(c[2]), "+f"(c[3])
        : "r"(a[0]), "r"(a[1]), "r"(a[2]), "r"(a[3]), "r"(b[0]), "r"(b[1]));
}
__device__ __forceinline__ uint32_t ldsu32(const __half* p) {
    return *(const uint32_t*)p;
}

// ---------------------------------------------------------------------------
// Preprocess kernels
// ---------------------------------------------------------------------------
__global__ void conv_half(const float* __restrict__ in, __half* __restrict__ out) {
    int i = blockIdx.x * blockDim.x + threadIdx.x;   // one float4
    float4 v = ((const float4*)in)[i];
    __half2* o = (__half2*)out + i * 2;
    o[0] = __floats2half2_rn(v.x, v.y);
    o[1] = __floats2half2_rn(v.z, v.w);
}

// fp32 [k][n] -> fp16 transposed [n][k]  (1024x1024)
__global__ void transpose_w(const float* __restrict__ in, __half* __restrict__ out) {
    __shared__ __half t[32][33];
    int x = blockIdx.x * 32 + threadIdx.x;
    int y0 = blockIdx.y * 32;
#pragma unroll
    for (int i = 0; i < 32; i += 8)
        t[threadIdx.y + i][threadIdx.x] =
            __float2half_rn(in[(size_t)(y0 + threadIdx.y + i) * Dv + x]);
    __syncthreads();
    int ox = blockIdx.y * 32 + threadIdx.x;
    int oy0 = blockIdx.x * 32;
#pragma unroll
    for (int i = 0; i < 32; i += 8)
        out[(size_t)(oy0 + threadIdx.y + i) * Dv + ox] = t[threadIdx.x][threadIdx.y + i];
}

// ---------------------------------------------------------------------------
// fp16 mma GEMM: C[4096,1024] = A_h @ Wt_h[n][k]^T. CTA 128x128, BK=64,
// 256 thr (8 warps 2x4 -> 64x32 warp tiles). Double-buffer cp.async.
// ---------------------------------------------------------------------------
#define GS 72
#define G_TILE_H (128 * GS)
#define GEMM_SMEM (4 * G_TILE_H * 2)   // 73728 B

__global__ __launch_bounds__(256, 2)
void h16_gemm(const __half* __restrict__ A,
              const __half* __restrict__ w0, const __half* __restrict__ w1,
              const __half* __restrict__ w2,
              void* __restrict__ c0, void* __restrict__ c1, void* __restrict__ c2,
              const float* __restrict__ bias, float qscale, int tz, int f32out) {
    extern __shared__ __half smh[];
    __half* Asb[2] = {smh, smh + G_TILE_H};
    __half* Bsb[2] = {smh + 2 * G_TILE_H, smh + 3 * G_TILE_H};

    const int tid  = threadIdx.x;
    const int wid  = tid >> 5;
    const int lane = tid & 31;
    const int g = lane >> 2;
    const int t = lane & 3;
    const int z = blockIdx.z;

    const __half* W = (z == 0) ? w0 : (z == 1) ? w1 : w2;
    void* C = (z == 0) ? c0 : (z == 1) ? c1 : c2;

    const int n0 = blockIdx.x * 128;
    const int m0 = blockIdx.y * 128;
    const int warp_m0 = (wid >> 2) * 64;
    const int warp_n0 = (wid & 3) * 32;

    float acc[4][4][4];
#pragma unroll
    for (int mt = 0; mt < 4; mt++)
#pragma unroll
        for (int nt = 0; nt < 4; nt++)
#pragma unroll
            for (int e = 0; e < 4; e++) acc[mt][nt][e] = 0.f;

    auto prefetch = [&](int chunk, int buf) {
        const int k0 = chunk * 64;
        const uint32_t as = smem_u32(Asb[buf]);
        const uint32_t bs = smem_u32(Bsb[buf]);
        const __half* Ag = A + (size_t)m0 * Dv + k0;
        const __half* Bg = W + (size_t)n0 * Dv + k0;
#pragma unroll
        for (int it = 0; it < 4; it++) {
            int idx = it * 256 + tid;
            int r = idx >> 3, c = idx & 7;
            CP16(as + (uint32_t)(r * GS + c * 8) * 2, Ag + (size_t)r * Dv + c * 8);
        }
#pragma unroll
        for (int it = 0; it < 4; it++) {
            int idx = it * 256 + tid;
            int r = idx >> 3, c = idx & 7;
            CP16(bs + (uint32_t)(r * GS + c * 8) * 2, Bg + (size_t)r * Dv + c * 8);
        }
    };

    prefetch(0, 0); CP_COMMIT();
    prefetch(1, 1); CP_COMMIT();

    for (int chunk = 0; chunk < Dv / 64; chunk++) {
        const int buf = chunk & 1;
        CP_WAIT1();
        __syncthreads();

        const __half* As = Asb[buf];
        const __half* Bs = Bsb[buf];
#pragma unroll
        for (int kk = 0; kk < 4; kk++) {
            uint32_t af[4][4];
#pragma unroll
            for (int mt = 0; mt < 4; mt++) {
                const __half* p = As + (warp_m0 + mt * 16 + g) * GS + kk * 16 + 2 * t;
                af[mt][0] = ldsu32(p);
                af[mt][1] = ldsu32(p + 8 * GS);
                af[mt][2] = ldsu32(p + 8);
                af[mt][3] = ldsu32(p + 8 * GS + 8);
            }
            uint32_t bf[4][2];
#pragma unroll
            for (int nt = 0; nt < 4; nt++) {
                const __half* p = Bs + (warp_n0 + nt * 8 + g) * GS + kk * 16 + 2 * t;
                bf[nt][0] = ldsu32(p);
                bf[nt][1] = ldsu32(p + 8);
            }
#pragma unroll
            for (int mt = 0; mt < 4; mt++)
#pragma unroll
                for (int nt = 0; nt < 4; nt++)
                    mma_f16(acc[mt][nt], af[mt], bf[nt]);
        }
        __syncthreads();

        if (chunk + 2 < Dv / 64) prefetch(chunk + 2, buf);
        CP_COMMIT();
    }

    const float sc = (z == 0) ? qscale : 1.0f;
#pragma unroll
    for (int mt = 0; mt < 4; mt++) {
        const int rm = m0 + warp_m0 + mt * 16 + g;
#pragma unroll
        for (int nt = 0; nt < 4; nt++) {
            const int cn = n0 + warp_n0 + nt * 8 + 2 * t;
            float a0 = acc[mt][nt][0], a1 = acc[mt][nt][1];
            float a2 = acc[mt][nt][2], a3 = acc[mt][nt][3];
            if (f32out) {
                float b0 = bias[cn], b1 = bias[cn + 1];
                float* Cf = (float*)C;
                *(float2*)(Cf + (size_t)rm * Dv + cn) = make_float2(a0 + b0, a1 + b1);
                *(float2*)(Cf + (size_t)(rm + 8) * Dv + cn) = make_float2(a2 + b0, a3 + b1);
            } else if (z == tz) {
                __half* Ct = (__half*)C;   // vt[d][token]
                Ct[(size_t)cn * Mv + rm]           = __float2half_rn(a0);
                Ct[(size_t)(cn + 1) * Mv + rm]     = __float2half_rn(a1);
                Ct[(size_t)cn * Mv + rm + 8]       = __float2half_rn(a2);
                Ct[(size_t)(cn + 1) * Mv + rm + 8] = __float2half_rn(a3);
            } else {
                __half2* Ch = (__half2*)C;
                Ch[((size_t)rm * Dv + cn) >> 1] = __floats2half2_rn(a0 * sc, a1 * sc);
                Ch[((size_t)(rm + 8) * Dv + cn) >> 1] = __floats2half2_rn(a2 * sc, a3 * sc);
            }
        }
    }
}

// ---------------------------------------------------------------------------
// fp16 mma flash attention. Grid (S/128, H, B), 256 thr; warp w: queries
// w*16..+15. 64-key tiles double-buffered; softmax base-2 (log2e folded into
// Q-projection scale and mask FMA); V consumed transposed [d][token].
// ---------------------------------------------------------------------------
#define AS 72
#define OFFK 0
#define OFFV (2 * 64 * AS)
#define OFFP (OFFV + 2 * 64 * AS)
#define OFFM_B ((OFFP + 128 * AS) * 2)
#define ATTN_SMEM (OFFM_B + 2 * 64 * 4)   // 55808 B

__global__ __launch_bounds__(256, 2)
void attn_h16(const __half* __restrict__ q,
              const __half* __restrict__ k,
              const __half* __restrict__ vt,
              const float* __restrict__ mask,
              __half* __restrict__ ctx) {
    extern __shared__ __half smh[];
    __half* KsB = smh + OFFK;
    __half* VsB = smh + OFFV;
    __half* Ps  = smh + OFFP;
    float* MkB  = (float*)((char*)smh + OFFM_B);

    const int tid  = threadIdx.x;
    const int wid  = tid >> 5;
    const int lane = tid & 31;
    const int g = lane >> 2;
    const int t = lane & 3;
    const int b  = blockIdx.z;
    const int h  = blockIdx.y;
    const int q0 = blockIdx.x * 128;
    const int row0 = wid * 16;

    auto prefetch = [&](int it) {
        const int buf = it & 1;
        const int k0 = it * 64;
        const uint32_t ks = smem_u32(KsB + buf * 64 * AS);
        const uint32_t vs = smem_u32(VsB + buf * 64 * AS);
        const __half* kg = k + (size_t)(b * Sv + k0) * Dv + h * DHv;
        const __half* vg = vt + (size_t)(h * DHv) * Mv + b * Sv + k0;
#pragma unroll
        for (int p = 0; p < 2; p++) {
            int idx = p * 256 + tid;
            int r = idx >> 3, c = idx & 7;
            CP16(ks + (uint32_t)(r * AS + c * 8) * 2, kg + (size_t)r * Dv + c * 8);
        }
#pragma unroll
        for (int p = 0; p < 2; p++) {
            int idx = p * 256 + tid;
            int r = idx >> 3, c = idx & 7;
            CP16(vs + (uint32_t)(r * AS + c * 8) * 2, vg + (size_t)r * Mv + c * 8);
        }
        if (tid < 16)
            CP16(smem_u32(MkB + buf * 64 + tid * 4), mask + b * Sv + k0 + tid * 4);
    };

    prefetch(0); CP_COMMIT();
    prefetch(1); CP_COMMIT();

    // Stage Q tile, extract A-fragments (scale pre-folded in projection)
    {
        const __half* qg = q + (size_t)(b * Sv + q0) * Dv + h * DHv;
#pragma unroll
        for (int p = 0; p < 4; p++) {
            int idx = p * 256 + tid;
            int r = idx >> 3, c = idx & 7;
            *(uint4*)(Ps + r * AS + c * 8) = *(const uint4*)(qg + (size_t)r * Dv + c * 8);
        }
    }
    __syncthreads();

    uint32_t qf[4][4];
#pragma unroll
    for (int kk = 0; kk < 4; kk++) {
        const __half* p = Ps + (row0 + g) * AS + kk * 16 + 2 * t;
        qf[kk][0] = ldsu32(p);
        qf[kk][1] = ldsu32(p + 8 * AS);
        qf[kk][2] = ldsu32(p + 8);
        qf[kk][3] = ldsu32(p + 8 * AS + 8);
    }
    __syncthreads();

    float m_lo = -1e30f, m_hi = -1e30f, l_lo = 0.f, l_hi = 0.f;
    float acc[8][4];
#pragma unroll
    for (int nt = 0; nt < 8; nt++)
#pragma unroll
        for (int e = 0; e < 4; e++) acc[nt][e] = 0.f;

    __half* PsW = Ps + row0 * AS;

    for (int it = 0; it < Sv / 64; it++) {
        const int buf = it & 1;
        const __half* Ks = KsB + buf * 64 * AS;
        const __half* Vs = VsB + buf * 64 * AS;
        const float* Mk = MkB + buf * 64;

        CP_WAIT1();
        __syncthreads();

        float s[8][4];
#pragma unroll
        for (int nt = 0; nt < 8; nt++)
#pragma unroll
            for (int e = 0; e < 4; e++) s[nt][e] = 0.f;

#pragma unroll
        for (int kk = 0; kk < 4; kk++) {
            uint32_t bf[8][2];
#pragma unroll
            for (int nt = 0; nt < 8; nt++) {
                const __half* p = Ks + (nt * 8 + g) * AS + kk * 16 + 2 * t;
                bf[nt][0] = ldsu32(p);
                bf[nt][1] = ldsu32(p + 8);
            }
#pragma unroll
            for (int nt = 0; nt < 8; nt++)
                mma_f16(s[nt], qf[kk], bf[nt]);
        }

        float tmax_lo = -1e30f, tmax_hi = -1e30f;
#pragma unroll
        for (int nt = 0; nt < 8; nt++) {
            float mv0 = Mk[nt * 8 + 2 * t];
            float mv1 = Mk[nt * 8 + 2 * t + 1];
            s[nt][0] = fmaf(mv0, LOG2E, s[nt][0]);
            s[nt][1] = fmaf(mv1, LOG2E, s[nt][1]);
            s[nt][2] = fmaf(mv0, LOG2E, s[nt][2]);
            s[nt][3] = fmaf(mv1, LOG2E, s[nt][3]);
            tmax_lo = fmaxf(tmax_lo, fmaxf(s[nt][0], s[nt][1]));
            tmax_hi = fmaxf(tmax_hi, fmaxf(s[nt][2], s[nt][3]));
        }
#pragma unroll
        for (int o = 1; o < 4; o <<= 1) {
            tmax_lo = fmaxf(tmax_lo, __shfl_xor_sync(0xffffffffu, tmax_lo, o));
            tmax_hi = fmaxf(tmax_hi, __shfl_xor_sync(0xffffffffu, tmax_hi, o));
        }
        float nm_lo = fmaxf(m_lo, tmax_lo);
        float nm_hi = fmaxf(m_hi, tmax_hi);
        float cr_lo = ex2f(m_lo - nm_lo);
        float cr_hi = ex2f(m_hi - nm_hi);
        m_lo = nm_lo; m_hi = nm_hi;

        float sum_lo = 0.f, sum_hi = 0.f;
#pragma unroll
        for (int nt = 0; nt < 8; nt++) {
            s[nt][0] = ex2f(s[nt][0] - nm_lo);
            s[nt][1] = ex2f(s[nt][1] - nm_lo);
            s[nt][2] = ex2f(s[nt][2] - nm_hi);
            s[nt][3] = ex2f(s[nt][3] - nm_hi);
            sum_lo += s[nt][0] + s[nt][1];
            sum_hi += s[nt][2] + s[nt][3];
        }
#pragma unroll
        for (int o = 1; o < 4; o <<= 1) {
            sum_lo += __shfl_xor_sync(0xffffffffu, sum_lo, o);
            sum_hi += __shfl_xor_sync(0xffffffffu, sum_hi, o);
        }
        l_lo = l_lo * cr_lo + sum_lo;
        l_hi = l_hi * cr_hi + sum_hi;

#pragma unroll
        for (int nt = 0; nt < 8; nt++) {
            acc[nt][0] *= cr_lo; acc[nt][1] *= cr_lo;
            acc[nt][2] *= cr_hi; acc[nt][3] *= cr_hi;
            *(__half2*)(PsW + g * AS + nt * 8 + 2 * t) =
                __floats2half2_rn(s[nt][0], s[nt][1]);
            *(__half2*)(PsW + (g + 8) * AS + nt * 8 + 2 * t) =
                __floats2half2_rn(s[nt][2], s[nt][3]);
        }
        __syncwarp();

#pragma unroll
        for (int kk = 0; kk < 4; kk++) {
            uint32_t af[4];
            const __half* pp = PsW + g * AS + kk * 16 + 2 * t;
            af[0] = ldsu32(pp);
            af[1] = ldsu32(pp + 8 * AS);
            af[2] = ldsu32(pp + 8);
            af[3] = ldsu32(pp + 8 * AS + 8);
#pragma unroll
            for (int nt = 0; nt < 8; nt++) {
                uint32_t bf[2];
                const __half* p = Vs + (nt * 8 + g) * AS + kk * 16 + 2 * t;
                bf[0] = ldsu32(p);
                bf[1] = ldsu32(p + 8);
                mma_f16(acc[nt], af, bf);
            }
        }
        __syncthreads();

        if (it + 2 < Sv / 64) prefetch(it + 2);
        CP_COMMIT();
    }

    const float inv_lo = 1.0f / l_lo;
    const float inv_hi = 1.0f / l_hi;
    __half* c0 = ctx + (size_t)(b * Sv + q0 + row0 + g) * Dv + h * DHv;
    __half* c1 = ctx + (size_t)(b * Sv + q0 + row0 + 8 + g) * Dv + h * DHv;
#pragma unroll
    for (int nt = 0; nt < 8; nt++) {
        int cn = nt * 8 + 2 * t;
        *(__half2*)(c0 + cn) = __floats2half2_rn(acc[nt][0] * inv_lo, acc[nt][1] * inv_lo);
        *(__half2*)(c1 + cn) = __floats2half2_rn(acc[nt][2] * inv_hi, acc[nt][3] * inv_hi);
    }
}

// ---------------------------------------------------------------------------
// Launch
// ---------------------------------------------------------------------------
extern "C" void kernel_launch(void* const* d_in, const int* in_sizes, int n_in,
                              void* d_out, int out_size) {
    const float* x    = (const float*)d_in[0];
    const float* mask = (const float*)d_in[1];
    const float* Wq   = (const float*)d_in[2];
    const float* Wk   = (const float*)d_in[3];
    const float* Wv   = (const float*)d_in[4];
    const float* Wo   = (const float*)d_in[5];
    const float* bo   = (const float*)d_in[6];
    float* out = (float*)d_out;

    __half *xh, *qh, *kh, *vt, *ctxh, *wqt, *wkt, *wvt, *wot;
    cudaGetSymbolAddress((void**)&xh,   g_xh);
    cudaGetSymbolAddress((void**)&qh,   g_qh);
    cudaGetSymbolAddress((void**)&kh,   g_kh);
    cudaGetSymbolAddress((void**)&vt,   g_vt);
    cudaGetSymbolAddress((void**)&ctxh, g_ctxh);
    cudaGetSymbolAddress((void**)&wqt,  g_wqt);
    cudaGetSymbolAddress((void**)&wkt,  g_wkt);
    cudaGetSymbolAddress((void**)&wvt,  g_wvt);
    cudaGetSymbolAddress((void**)&wot,  g_wot);

    conv_half<<<(Mv * Dv / 4) / 256, 256>>>(x, xh);
    dim3 tg(32, 32), tb(32, 8);
    transpose_w<<<tg, tb>>>(Wq, wqt);
    transpose_w<<<tg, tb>>>(Wk, wkt);
    transpose_w<<<tg, tb>>>(Wv, wvt);
    transpose_w<<<tg, tb>>>(Wo, wot);

    cudaFuncSetAttribute(h16_gemm,
                         cudaFuncAttributeMaxDynamicSharedMemorySize, GEMM_SMEM);
    cudaFuncSetAttribute(attn_h16,
                         cudaFuncAttributeMaxDynamicSharedMemorySize, ATTN_SMEM);

    const float qscale = LOG2E / 32.0f;
    h16_gemm<<<dim3(Dv / 128, Mv / 128, 3), 256, GEMM_SMEM>>>(
        xh, wqt, wkt, wvt, qh, kh, vt, nullptr, qscale, 2, 0);

    attn_h16<<<dim3(Sv / 128, Hv, Bv), 256, ATTN_SMEM>>>(qh, kh, vt, mask, ctxh);

    h16_gemm<<<dim3(Dv / 128, Mv / 128, 1), 256, GEMM_SMEM>>>(
        ctxh, wot, wot, wot, out, out, out, bo, 1.0f, -1, 1);
}

// round 6
// speedup vs baseline: 8.0269x; 1.2459x over previous
#include <cuda_runtime.h>
#include <cuda_fp16.h>
#include <cstdint>
#include <math.h>

// Problem constants
#define Bv  2
#define Sv  2048
#define Dv  1024
#define Hv  16
#define DHv 64
#define Mv  (Bv * Sv)   // 4096

#define LOG2E 1.4426950408889634f

// Scratch (__device__ globals)
__device__ __half g_xh[Mv * Dv];
__device__ __half g_qh[Mv * Dv];
__device__ __half g_kh[Mv * Dv];
__device__ __half g_vt[Dv * Mv];      // V transposed: [d][token]
__device__ __half g_ctxh[Mv * Dv];
__device__ __half g_wqt[Dv * Dv];     // W transposed fp16: [n][k]
__device__ __half g_wkt[Dv * Dv];
__device__ __half g_wvt[Dv * Dv];
__device__ __half g_wot[Dv * Dv];

// ---------------------------------------------------------------------------
// Helpers (arch-generic PTX: mma.sync f16 + cp.async + ldmatrix)
// ---------------------------------------------------------------------------
__device__ __forceinline__ uint32_t smem_u32(const void* p) {
    uint32_t a;
    asm("{ .reg .u64 t; cvta.to.shared.u64 t, %1; cvt.u32.u64 %0, t; }" : "=r"(a) : "l"(p));
    return a;
}
#define CP16(dst, src) \
    asm volatile("cp.async.cg.shared.global [%0], [%1], 16;" :: "r"(dst), "l"(src))
#define CP_COMMIT() asm volatile("cp.async.commit_group;" ::: "memory")
#define CP_WAIT1()  asm volatile("cp.async.wait_group 1;" ::: "memory")
#define CP_WAIT2()  asm volatile("cp.async.wait_group 2;" ::: "memory")

__device__ __forceinline__ float ex2f(float x) {
    float r;
    asm("ex2.approx.f32 %0, %1;" : "=f"(r) : "f"(x));
    return r;
}
__device__ __forceinline__ void mma_f16(float c[4], const uint32_t a[4],
                                        const uint32_t b[2]) {
    asm volatile(
        "mma.sync.aligned.m16n8k16.row.col.f32.f16.f16.f32 "
        "{%0,%1,%2,%3}, {%4,%5,%6,%7}, {%8,%9}, {%0,%1,%2,%3};"
        : "+f"(c[0]), "+f"(c[1]), "+f"(c[2]), "+f"(c[3])
        : "r"(a[0]), "r"(a[1]), "r"(a[2]), "r"(a[3]), "r"(b[0]), "r"(b[1]));
}
__device__ __forceinline__ void ldm_x4(uint32_t r[4], uint32_t addr) {
    asm volatile(
        "ldmatrix.sync.aligned.m8n8.x4.shared.b16 {%0,%1,%2,%3}, [%4];"
        : "=r"(r[0]), "=r"(r[1]), "=r"(r[2]), "=r"(r[3]) : "r"(addr));
}

// ---------------------------------------------------------------------------
// Preprocess kernels
// ---------------------------------------------------------------------------
__global__ void conv_half(const float* __restrict__ in, __half* __restrict__ out) {
    int i = blockIdx.x * blockDim.x + threadIdx.x;   // one float4
    float4 v = ((const float4*)in)[i];
    __half2* o = (__half2*)out + i * 2;
    o[0] = __floats2half2_rn(v.x, v.y);
    o[1] = __floats2half2_rn(v.z, v.w);
}

// 4 weight transposes in one launch (z selects). fp32 [k][n] -> fp16 [n][k].
__global__ void transpose_w4(const float* __restrict__ w0, const float* __restrict__ w1,
                             const float* __restrict__ w2, const float* __restrict__ w3,
                             __half* __restrict__ o0, __half* __restrict__ o1,
                             __half* __restrict__ o2, __half* __restrict__ o3) {
    const float* in  = (blockIdx.z == 0) ? w0 : (blockIdx.z == 1) ? w1
                     : (blockIdx.z == 2) ? w2 : w3;
    __half* out = (blockIdx.z == 0) ? o0 : (blockIdx.z == 1) ? o1
                : (blockIdx.z == 2) ? o2 : o3;
    __shared__ __half t[32][33];
    int x = blockIdx.x * 32 + threadIdx.x;
    int y0 = blockIdx.y * 32;
#pragma unroll
    for (int i = 0; i < 32; i += 8)
        t[threadIdx.y + i][threadIdx.x] =
            __float2half_rn(in[(size_t)(y0 + threadIdx.y + i) * Dv + x]);
    __syncthreads();
    int ox = blockIdx.y * 32 + threadIdx.x;
    int oy0 = blockIdx.x * 32;
#pragma unroll
    for (int i = 0; i < 32; i += 8)
        out[(size_t)(oy0 + threadIdx.y + i) * Dv + ox] = t[threadIdx.x][threadIdx.y + i];
}

// ---------------------------------------------------------------------------
// fp16 mma GEMM: C[4096,1024] = A_h @ Wt_h[n][k]^T. CTA 128x128, BK=64,
// 256 thr (8 warps 2x4 -> 64x32). 3-stage cp.async pipeline, XOR-swizzled
// 64-half rows, ldmatrix fragment loads.
// ---------------------------------------------------------------------------
// swizzled offset in halves: row r (64-wide), 8-half chunk c
#define SWZ(r, c) (((r) << 6) + (((c) ^ ((r) & 7)) << 3))
#define STAGE_H (2 * 128 * 64)                 // A+B halves per stage
#define GEMM_SMEM (3 * STAGE_H * 2)            // 98304 B

__global__ __launch_bounds__(256, 2)
void h16_gemm(const __half* __restrict__ A,
              const __half* __restrict__ w0, const __half* __restrict__ w1,
              const __half* __restrict__ w2,
              void* __restrict__ c0, void* __restrict__ c1, void* __restrict__ c2,
              const float* __restrict__ bias, float qscale, int tz, int f32out) {
    extern __shared__ __half smh[];

    const int tid  = threadIdx.x;
    const int wid  = tid >> 5;
    const int lane = tid & 31;
    const int g = lane >> 2;
    const int t = lane & 3;
    const int quad = lane >> 3;     // 0..3
    const int rb = lane & 7;        // row within 8
    const int q1 = quad & 1;
    const int q2 = quad >> 1;
    const int z = blockIdx.z;

    const __half* W = (z == 0) ? w0 : (z == 1) ? w1 : w2;
    void* C = (z == 0) ? c0 : (z == 1) ? c1 : c2;

    const int n0 = blockIdx.x * 128;
    const int m0 = blockIdx.y * 128;
    const int warp_m0 = (wid >> 2) * 64;
    const int warp_n0 = (wid & 3) * 32;

    const uint32_t smem_b = smem_u32(smh);

    float acc[4][4][4];
#pragma unroll
    for (int mt = 0; mt < 4; mt++)
#pragma unroll
        for (int nt = 0; nt < 4; nt++)
#pragma unroll
            for (int e = 0; e < 4; e++) acc[mt][nt][e] = 0.f;

    auto prefetch = [&](int chunk, int buf) {
        const int k0 = chunk * 64;
        const uint32_t as = smem_b + buf * STAGE_H * 2;
        const uint32_t bs = as + 128 * 64 * 2;
        const __half* Ag = A + (size_t)m0 * Dv + k0;
        const __half* Bg = W + (size_t)n0 * Dv + k0;
#pragma unroll
        for (int it = 0; it < 4; it++) {
            int idx = it * 256 + tid;
            int r = idx >> 3, c = idx & 7;
            CP16(as + SWZ(r, c) * 2, Ag + (size_t)r * Dv + c * 8);
        }
#pragma unroll
        for (int it = 0; it < 4; it++) {
            int idx = it * 256 + tid;
            int r = idx >> 3, c = idx & 7;
            CP16(bs + SWZ(r, c) * 2, Bg + (size_t)r * Dv + c * 8);
        }
    };

    prefetch(0, 0); CP_COMMIT();
    prefetch(1, 1); CP_COMMIT();
    prefetch(2, 2); CP_COMMIT();

    for (int chunk = 0; chunk < Dv / 64; chunk++) {
        const int buf = (chunk % 3);
        CP_WAIT2();
        __syncthreads();

        const uint32_t as = smem_b + buf * STAGE_H * 2;
        const uint32_t bs = as + 128 * 64 * 2;

#pragma unroll
        for (int kk = 0; kk < 4; kk++) {
            // A fragments: matrix quads (rows +q1*8, chunk +q2)
            uint32_t af[4][4];
#pragma unroll
            for (int mt = 0; mt < 4; mt++) {
                int row = warp_m0 + mt * 16 + q1 * 8 + rb;
                uint32_t off = (uint32_t)((row << 6) + (((kk * 2 + q2) ^ rb) << 3));
                ldm_x4(af[mt], as + off * 2);
            }
            // B fragments: matrix quads (rows +q2*8, chunk +q1); 2 nt per x4
            uint32_t bfr[2][4];
#pragma unroll
            for (int ntp = 0; ntp < 2; ntp++) {
                int row = warp_n0 + ntp * 16 + q2 * 8 + rb;
                uint32_t off = (uint32_t)((row << 6) + (((kk * 2 + q1) ^ rb) << 3));
                ldm_x4(bfr[ntp], bs + off * 2);
            }
#pragma unroll
            for (int mt = 0; mt < 4; mt++)
#pragma unroll
                for (int nt = 0; nt < 4; nt++)
                    mma_f16(acc[mt][nt], af[mt], &bfr[nt >> 1][(nt & 1) * 2]);
        }
        __syncthreads();

        if (chunk + 3 < Dv / 64) prefetch(chunk + 3, buf);
        CP_COMMIT();
    }

    const float sc = (z == 0) ? qscale : 1.0f;
#pragma unroll
    for (int mt = 0; mt < 4; mt++) {
        const int rm = m0 + warp_m0 + mt * 16 + g;
#pragma unroll
        for (int nt = 0; nt < 4; nt++) {
            const int cn = n0 + warp_n0 + nt * 8 + 2 * t;
            float a0 = acc[mt][nt][0], a1 = acc[mt][nt][1];
            float a2 = acc[mt][nt][2], a3 = acc[mt][nt][3];
            if (f32out) {
                float b0 = bias[cn], b1 = bias[cn + 1];
                float* Cf = (float*)C;
                *(float2*)(Cf + (size_t)rm * Dv + cn) = make_float2(a0 + b0, a1 + b1);
                *(float2*)(Cf + (size_t)(rm + 8) * Dv + cn) = make_float2(a2 + b0, a3 + b1);
            } else if (z == tz) {
                __half* Ct = (__half*)C;   // vt[d][token]
                Ct[(size_t)cn * Mv + rm]           = __float2half_rn(a0);
                Ct[(size_t)(cn + 1) * Mv + rm]     = __float2half_rn(a1);
                Ct[(size_t)cn * Mv + rm + 8]       = __float2half_rn(a2);
                Ct[(size_t)(cn + 1) * Mv + rm + 8] = __float2half_rn(a3);
            } else {
                __half2* Ch = (__half2*)C;
                Ch[((size_t)rm * Dv + cn) >> 1] = __floats2half2_rn(a0 * sc, a1 * sc);
                Ch[((size_t)(rm + 8) * Dv + cn) >> 1] = __floats2half2_rn(a2 * sc, a3 * sc);
            }
        }
    }
}

// ---------------------------------------------------------------------------
// fp16 mma flash attention, ldmatrix fragment loads. Grid (S/128, H, B),
// 256 thr; warp w: queries w*16..+15. 64-key tiles double-buffered; softmax
// base-2 (log2e folded into Q projection and mask FMA); V transposed.
// Padded stride 72 halves (144B): ldmatrix rows -> 8 distinct bank groups.
// ---------------------------------------------------------------------------
#define AS 72
#define OFFK 0
#define OFFV (2 * 64 * AS)
#define OFFP (OFFV + 2 * 64 * AS)
#define OFFM_B ((OFFP + 128 * AS) * 2)
#define ATTN_SMEM (OFFM_B + 2 * 64 * 4)   // 55808 B

__global__ __launch_bounds__(256, 2)
void attn_h16(const __half* __restrict__ q,
              const __half* __restrict__ k,
              const __half* __restrict__ vt,
              const float* __restrict__ mask,
              __half* __restrict__ ctx) {
    extern __shared__ __half smh[];
    __half* KsB = smh + OFFK;
    __half* VsB = smh + OFFV;
    __half* Ps  = smh + OFFP;
    float* MkB  = (float*)((char*)smh + OFFM_B);

    const int tid  = threadIdx.x;
    const int wid  = tid >> 5;
    const int lane = tid & 31;
    const int g = lane >> 2;
    const int t = lane & 3;
    const int quad = lane >> 3;
    const int rb = lane & 7;
    const int q1 = quad & 1;
    const int q2 = quad >> 1;
    const int b  = blockIdx.z;
    const int h  = blockIdx.y;
    const int q0 = blockIdx.x * 128;
    const int row0 = wid * 16;

    const uint32_t ks_b = smem_u32(KsB);
    const uint32_t vs_b = smem_u32(VsB);
    const uint32_t ps_b = smem_u32(Ps);
    const uint32_t psw_b = ps_b + (uint32_t)(row0 * AS) * 2;

    auto prefetch = [&](int it) {
        const int buf = it & 1;
        const int k0 = it * 64;
        const uint32_t ks = ks_b + (uint32_t)(buf * 64 * AS) * 2;
        const uint32_t vs = vs_b + (uint32_t)(buf * 64 * AS) * 2;
        const __half* kg = k + (size_t)(b * Sv + k0) * Dv + h * DHv;
        const __half* vg = vt + (size_t)(h * DHv) * Mv + b * Sv + k0;
#pragma unroll
        for (int p = 0; p < 2; p++) {
            int idx = p * 256 + tid;
            int r = idx >> 3, c = idx & 7;
            CP16(ks + (uint32_t)(r * AS + c * 8) * 2, kg + (size_t)r * Dv + c * 8);
        }
#pragma unroll
        for (int p = 0; p < 2; p++) {
            int idx = p * 256 + tid;
            int r = idx >> 3, c = idx & 7;
            CP16(vs + (uint32_t)(r * AS + c * 8) * 2, vg + (size_t)r * Mv + c * 8);
        }
        if (tid < 16)
            CP16(smem_u32(MkB + buf * 64 + tid * 4), mask + b * Sv + k0 + tid * 4);
    };

    prefetch(0); CP_COMMIT();
    prefetch(1); CP_COMMIT();

    // Stage Q tile, extract A-fragments via ldmatrix
    {
        const __half* qg = q + (size_t)(b * Sv + q0) * Dv + h * DHv;
#pragma unroll
        for (int p = 0; p < 4; p++) {
            int idx = p * 256 + tid;
            int r = idx >> 3, c = idx & 7;
            *(uint4*)(Ps + r * AS + c * 8) = *(const uint4*)(qg + (size_t)r * Dv + c * 8);
        }
    }
    __syncthreads();

    uint32_t qf[4][4];
#pragma unroll
    for (int kk = 0; kk < 4; kk++) {
        uint32_t off = (uint32_t)((row0 + q1 * 8 + rb) * AS + kk * 16 + q2 * 8);
        ldm_x4(qf[kk], ps_b + off * 2);
    }
    __syncthreads();

    float m_lo = -1e30f, m_hi = -1e30f, l_lo = 0.f, l_hi = 0.f;
    float acc[8][4];
#pragma unroll
    for (int nt = 0; nt < 8; nt++)
#pragma unroll
        for (int e = 0; e < 4; e++) acc[nt][e] = 0.f;

    __half* PsW = Ps + row0 * AS;

    for (int it = 0; it < Sv / 64; it++) {
        const int buf = it & 1;
        const uint32_t ks = ks_b + (uint32_t)(buf * 64 * AS) * 2;
        const uint32_t vs = vs_b + (uint32_t)(buf * 64 * AS) * 2;
        const float* Mk = MkB + buf * 64;

        CP_WAIT1();
        __syncthreads();

        // --- S = Q @ K^T ---
        float s[8][4];
#pragma unroll
        for (int nt = 0; nt < 8; nt++)
#pragma unroll
            for (int e = 0; e < 4; e++) s[nt][e] = 0.f;

#pragma unroll
        for (int kk = 0; kk < 4; kk++) {
            uint32_t bfr[4][4];
#pragma unroll
            for (int ntp = 0; ntp < 4; ntp++) {
                uint32_t off = (uint32_t)((ntp * 16 + q2 * 8 + rb) * AS + kk * 16 + q1 * 8);
                ldm_x4(bfr[ntp], ks + off * 2);
            }
#pragma unroll
            for (int nt = 0; nt < 8; nt++)
                mma_f16(s[nt], qf[kk], &bfr[nt >> 1][(nt & 1) * 2]);
        }

        // --- mask + online softmax (base 2) ---
        float tmax_lo = -1e30f, tmax_hi = -1e30f;
#pragma unroll
        for (int nt = 0; nt < 8; nt++) {
            float mv0 = Mk[nt * 8 + 2 * t];
            float mv1 = Mk[nt * 8 + 2 * t + 1];
            s[nt][0] = fmaf(mv0, LOG2E, s[nt][0]);
            s[nt][1] = fmaf(mv1, LOG2E, s[nt][1]);
            s[nt][2] = fmaf(mv0, LOG2E, s[nt][2]);
            s[nt][3] = fmaf(mv1, LOG2E, s[nt][3]);
            tmax_lo = fmaxf(tmax_lo, fmaxf(s[nt][0], s[nt][1]));
            tmax_hi = fmaxf(tmax_hi, fmaxf(s[nt][2], s[nt][3]));
        }
#pragma unroll
        for (int o = 1; o < 4; o <<= 1) {
            tmax_lo = fmaxf(tmax_lo, __shfl_xor_sync(0xffffffffu, tmax_lo, o));
            tmax_hi = fmaxf(tmax_hi, __shfl_xor_sync(0xffffffffu, tmax_hi, o));
        }
        float nm_lo = fmaxf(m_lo, tmax_lo);
        float nm_hi = fmaxf(m_hi, tmax_hi);
        float cr_lo = ex2f(m_lo - nm_lo);
        float cr_hi = ex2f(m_hi - nm_hi);
        m_lo = nm_lo; m_hi = nm_hi;

        float sum_lo = 0.f, sum_hi = 0.f;
#pragma unroll
        for (int nt = 0; nt < 8; nt++) {
            s[nt][0] = ex2f(s[nt][0] - nm_lo);
            s[nt][1] = ex2f(s[nt][1] - nm_lo);
            s[nt][2] = ex2f(s[nt][2] - nm_hi);
            s[nt][3] = ex2f(s[nt][3] - nm_hi);
            sum_lo += s[nt][0] + s[nt][1];
            sum_hi += s[nt][2] + s[nt][3];
        }
#pragma unroll
        for (int o = 1; o < 4; o <<= 1) {
            sum_lo += __shfl_xor_sync(0xffffffffu, sum_lo, o);
            sum_hi += __shfl_xor_sync(0xffffffffu, sum_hi, o);
        }
        l_lo = l_lo * cr_lo + sum_lo;
        l_hi = l_hi * cr_hi + sum_hi;

#pragma unroll
        for (int nt = 0; nt < 8; nt++) {
            acc[nt][0] *= cr_lo; acc[nt][1] *= cr_lo;
            acc[nt][2] *= cr_hi; acc[nt][3] *= cr_hi;
            *(__half2*)(PsW + g * AS + nt * 8 + 2 * t) =
                __floats2half2_rn(s[nt][0], s[nt][1]);
            *(__half2*)(PsW + (g + 8) * AS + nt * 8 + 2 * t) =
                __floats2half2_rn(s[nt][2], s[nt][3]);
        }
        __syncwarp();

        // --- acc += P @ V ---
#pragma unroll
        for (int kk = 0; kk < 4; kk++) {
            uint32_t af[4];
            {
                uint32_t off = (uint32_t)((q1 * 8 + rb) * AS + kk * 16 + q2 * 8);
                ldm_x4(af, psw_b + off * 2);
            }
            uint32_t bfr[4][4];
#pragma unroll
            for (int ntp = 0; ntp < 4; ntp++) {
                uint32_t off = (uint32_t)((ntp * 16 + q2 * 8 + rb) * AS + kk * 16 + q1 * 8);
                ldm_x4(bfr[ntp], vs + off * 2);
            }
#pragma unroll
            for (int nt = 0; nt < 8; nt++)
                mma_f16(acc[nt], af, &bfr[nt >> 1][(nt & 1) * 2]);
        }
        __syncthreads();

        if (it + 2 < Sv / 64) prefetch(it + 2);
        CP_COMMIT();
    }

    const float inv_lo = 1.0f / l_lo;
    const float inv_hi = 1.0f / l_hi;
    __half* c0 = ctx + (size_t)(b * Sv + q0 + row0 + g) * Dv + h * DHv;
    __half* c1 = ctx + (size_t)(b * Sv + q0 + row0 + 8 + g) * Dv + h * DHv;
#pragma unroll
    for (int nt = 0; nt < 8; nt++) {
        int cn = nt * 8 + 2 * t;
        *(__half2*)(c0 + cn) = __floats2half2_rn(acc[nt][0] * inv_lo, acc[nt][1] * inv_lo);
        *(__half2*)(c1 + cn) = __floats2half2_rn(acc[nt][2] * inv_hi, acc[nt][3] * inv_hi);
    }
}

// ---------------------------------------------------------------------------
// Launch
// ---------------------------------------------------------------------------
extern "C" void kernel_launch(void* const* d_in, const int* in_sizes, int n_in,
                              void* d_out, int out_size) {
    const float* x    = (const float*)d_in[0];
    const float* mask = (const float*)d_in[1];
    const float* Wq   = (const float*)d_in[2];
    const float* Wk   = (const float*)d_in[3];
    const float* Wv   = (const float*)d_in[4];
    const float* Wo   = (const float*)d_in[5];
    const float* bo   = (const float*)d_in[6];
    float* out = (float*)d_out;

    __half *xh, *qh, *kh, *vt, *ctxh, *wqt, *wkt, *wvt, *wot;
    cudaGetSymbolAddress((void**)&xh,   g_xh);
    cudaGetSymbolAddress((void**)&qh,   g_qh);
    cudaGetSymbolAddress((void**)&kh,   g_kh);
    cudaGetSymbolAddress((void**)&vt,   g_vt);
    cudaGetSymbolAddress((void**)&ctxh, g_ctxh);
    cudaGetSymbolAddress((void**)&wqt,  g_wqt);
    cudaGetSymbolAddress((void**)&wkt,  g_wkt);
    cudaGetSymbolAddress((void**)&wvt,  g_wvt);
    cudaGetSymbolAddress((void**)&wot,  g_wot);

    conv_half<<<(Mv * Dv / 4) / 256, 256>>>(x, xh);
    transpose_w4<<<dim3(32, 32, 4), dim3(32, 8)>>>(Wq, Wk, Wv, Wo,
                                                   wqt, wkt, wvt, wot);

    cudaFuncSetAttribute(h16_gemm,
                         cudaFuncAttributeMaxDynamicSharedMemorySize, GEMM_SMEM);
    cudaFuncSetAttribute(attn_h16,
                         cudaFuncAttributeMaxDynamicSharedMemorySize, ATTN_SMEM);

    const float qscale = LOG2E / 32.0f;
    h16_gemm<<<dim3(Dv / 128, Mv / 128, 3), 256, GEMM_SMEM>>>(
        xh, wqt, wkt, wvt, qh, kh, vt, nullptr, qscale, 2, 0);

    attn_h16<<<dim3(Sv / 128, Hv, Bv), 256, ATTN_SMEM>>>(qh, kh, vt, mask, ctxh);

    h16_gemm<<<dim3(Dv / 128, Mv / 128, 1), 256, GEMM_SMEM>>>(
        ctxh, wot, wot, wot, out, out, out, bo, 1.0f, -1, 1);
}

// round 7
// speedup vs baseline: 8.3558x; 1.0410x over previous
#include <cuda_runtime.h>
#include <cuda_fp16.h>
#include <cstdint>
#include <math.h>

// Problem constants
#define Bv  2
#define Sv  2048
#define Dv  1024
#define Hv  16
#define DHv 64
#define Mv  (Bv * Sv)   // 4096

#define LOG2E 1.4426950408889634f

// Scratch (__device__ globals)
__device__ __half g_xh[Mv * Dv];
__device__ __half g_qh[Mv * Dv];
__device__ __half g_kh[Mv * Dv];
__device__ __half g_vt[Dv * Mv];      // V transposed: [d][token]
__device__ __half g_ctxh[Mv * Dv];
__device__ __half g_wqt[Dv * Dv];     // W transposed fp16: [n][k]
__device__ __half g_wkt[Dv * Dv];
__device__ __half g_wvt[Dv * Dv];
__device__ __half g_wot[Dv * Dv];

// ---------------------------------------------------------------------------
// Helpers (arch-generic PTX: mma.sync f16 + cp.async + ldmatrix)
// ---------------------------------------------------------------------------
__device__ __forceinline__ uint32_t smem_u32(const void* p) {
    uint32_t a;
    asm("{ .reg .u64 t; cvta.to.shared.u64 t, %1; cvt.u32.u64 %0, t; }" : "=r"(a) : "l"(p));
    return a;
}
#define CP16(dst, src) \
    asm volatile("cp.async.cg.shared.global [%0], [%1], 16;" :: "r"(dst), "l"(src))
#define CP_COMMIT() asm volatile("cp.async.commit_group;" ::: "memory")
#define CP_WAIT1()  asm volatile("cp.async.wait_group 1;" ::: "memory")
#define CP_WAIT2()  asm volatile("cp.async.wait_group 2;" ::: "memory")

__device__ __forceinline__ float ex2f(float x) {
    float r;
    asm("ex2.approx.f32 %0, %1;" : "=f"(r) : "f"(x));
    return r;
}
// packed half2 exp2 (one MUFU instruction for 2 values)
__device__ __forceinline__ uint32_t h2ex2(uint32_t x) {
    uint32_t r;
    asm("ex2.approx.f16x2 %0, %1;" : "=r"(r) : "r"(x));
    return r;
}
__device__ __forceinline__ uint32_t pack_h2(float lo, float hi) {
    uint32_t r;
    asm("cvt.rn.f16x2.f32 %0, %2, %1;" : "=r"(r) : "f"(lo), "f"(hi));
    return r;
}
__device__ __forceinline__ void mma_f16(float c[4], const uint32_t a[4],
                                        const uint32_t b[2]) {
    asm volatile(
        "mma.sync.aligned.m16n8k16.row.col.f32.f16.f16.f32 "
        "{%0,%1,%2,%3}, {%4,%5,%6,%7}, {%8,%9}, {%0,%1,%2,%3};"
        : "+f"(c[0]), "+f"(c[1]), "+f"(c[2]), "+f"(c[3])
        : "r"(a[0]), "r"(a[1]), "r"(a[2]), "r"(a[3]), "r"(b[0]), "r"(b[1]));
}
__device__ __forceinline__ void ldm_x4(uint32_t r[4], uint32_t addr) {
    asm volatile(
        "ldmatrix.sync.aligned.m8n8.x4.shared.b16 {%0,%1,%2,%3}, [%4];"
        : "=r"(r[0]), "=r"(r[1]), "=r"(r[2]), "=r"(r[3]) : "r"(addr));
}

// ---------------------------------------------------------------------------
// Preprocess kernels
// ---------------------------------------------------------------------------
__global__ void conv_half(const float* __restrict__ in, __half* __restrict__ out) {
    int i = blockIdx.x * blockDim.x + threadIdx.x;   // one float4
    float4 v = ((const float4*)in)[i];
    __half2* o = (__half2*)out + i * 2;
    o[0] = __floats2half2_rn(v.x, v.y);
    o[1] = __floats2half2_rn(v.z, v.w);
}

// 4 weight transposes in one launch (z selects). fp32 [k][n] -> fp16 [n][k].
__global__ void transpose_w4(const float* __restrict__ w0, const float* __restrict__ w1,
                             const float* __restrict__ w2, const float* __restrict__ w3,
                             __half* __restrict__ o0, __half* __restrict__ o1,
                             __half* __restrict__ o2, __half* __restrict__ o3) {
    const float* in  = (blockIdx.z == 0) ? w0 : (blockIdx.z == 1) ? w1
                     : (blockIdx.z == 2) ? w2 : w3;
    __half* out = (blockIdx.z == 0) ? o0 : (blockIdx.z == 1) ? o1
                : (blockIdx.z == 2) ? o2 : o3;
    __shared__ __half t[32][33];
    int x = blockIdx.x * 32 + threadIdx.x;
    int y0 = blockIdx.y * 32;
#pragma unroll
    for (int i = 0; i < 32; i += 8)
        t[threadIdx.y + i][threadIdx.x] =
            __float2half_rn(in[(size_t)(y0 + threadIdx.y + i) * Dv + x]);
    __syncthreads();
    int ox = blockIdx.y * 32 + threadIdx.x;
    int oy0 = blockIdx.x * 32;
#pragma unroll
    for (int i = 0; i < 32; i += 8)
        out[(size_t)(oy0 + threadIdx.y + i) * Dv + ox] = t[threadIdx.x][threadIdx.y + i];
}

// ---------------------------------------------------------------------------
// fp16 mma GEMM (round-6, unchanged): CTA 128x128, BK=64, 3-stage cp.async,
// XOR-swizzled rows, ldmatrix fragments.
// ---------------------------------------------------------------------------
#define SWZ(r, c) (((r) << 6) + (((c) ^ ((r) & 7)) << 3))
#define STAGE_H (2 * 128 * 64)
#define GEMM_SMEM (3 * STAGE_H * 2)            // 98304 B

__global__ __launch_bounds__(256, 2)
void h16_gemm(const __half* __restrict__ A,
              const __half* __restrict__ w0, const __half* __restrict__ w1,
              const __half* __restrict__ w2,
              void* __restrict__ c0, void* __restrict__ c1, void* __restrict__ c2,
              const float* __restrict__ bias, float qscale, int tz, int f32out) {
    extern __shared__ __half smh[];

    const int tid  = threadIdx.x;
    const int wid  = tid >> 5;
    const int lane = tid & 31;
    const int g = lane >> 2;
    const int t = lane & 3;
    const int quad = lane >> 3;
    const int rb = lane & 7;
    const int q1 = quad & 1;
    const int q2 = quad >> 1;
    const int z = blockIdx.z;

    const __half* W = (z == 0) ? w0 : (z == 1) ? w1 : w2;
    void* C = (z == 0) ? c0 : (z == 1) ? c1 : c2;

    const int n0 = blockIdx.x * 128;
    const int m0 = blockIdx.y * 128;
    const int warp_m0 = (wid >> 2) * 64;
    const int warp_n0 = (wid & 3) * 32;

    const uint32_t smem_b = smem_u32(smh);

    float acc[4][4][4];
#pragma unroll
    for (int mt = 0; mt < 4; mt++)
#pragma unroll
        for (int nt = 0; nt < 4; nt++)
#pragma unroll
            for (int e = 0; e < 4; e++) acc[mt][nt][e] = 0.f;

    auto prefetch = [&](int chunk, int buf) {
        const int k0 = chunk * 64;
        const uint32_t as = smem_b + buf * STAGE_H * 2;
        const uint32_t bs = as + 128 * 64 * 2;
        const __half* Ag = A + (size_t)m0 * Dv + k0;
        const __half* Bg = W + (size_t)n0 * Dv + k0;
#pragma unroll
        for (int it = 0; it < 4; it++) {
            int idx = it * 256 + tid;
            int r = idx >> 3, c = idx & 7;
            CP16(as + SWZ(r, c) * 2, Ag + (size_t)r * Dv + c * 8);
        }
#pragma unroll
        for (int it = 0; it < 4; it++) {
            int idx = it * 256 + tid;
            int r = idx >> 3, c = idx & 7;
            CP16(bs + SWZ(r, c) * 2, Bg + (size_t)r * Dv + c * 8);
        }
    };

    prefetch(0, 0); CP_COMMIT();
    prefetch(1, 1); CP_COMMIT();
    prefetch(2, 2); CP_COMMIT();

    for (int chunk = 0; chunk < Dv / 64; chunk++) {
        const int buf = (chunk % 3);
        CP_WAIT2();
        __syncthreads();

        const uint32_t as = smem_b + buf * STAGE_H * 2;
        const uint32_t bs = as + 128 * 64 * 2;

#pragma unroll
        for (int kk = 0; kk < 4; kk++) {
            uint32_t af[4][4];
#pragma unroll
            for (int mt = 0; mt < 4; mt++) {
                int row = warp_m0 + mt * 16 + q1 * 8 + rb;
                uint32_t off = (uint32_t)((row << 6) + (((kk * 2 + q2) ^ rb) << 3));
                ldm_x4(af[mt], as + off * 2);
            }
            uint32_t bfr[2][4];
#pragma unroll
            for (int ntp = 0; ntp < 2; ntp++) {
                int row = warp_n0 + ntp * 16 + q2 * 8 + rb;
                uint32_t off = (uint32_t)((row << 6) + (((kk * 2 + q1) ^ rb) << 3));
                ldm_x4(bfr[ntp], bs + off * 2);
            }
#pragma unroll
            for (int mt = 0; mt < 4; mt++)
#pragma unroll
                for (int nt = 0; nt < 4; nt++)
                    mma_f16(acc[mt][nt], af[mt], &bfr[nt >> 1][(nt & 1) * 2]);
        }
        __syncthreads();

        if (chunk + 3 < Dv / 64) prefetch(chunk + 3, buf);
        CP_COMMIT();
    }

    const float sc = (z == 0) ? qscale : 1.0f;
#pragma unroll
    for (int mt = 0; mt < 4; mt++) {
        const int rm = m0 + warp_m0 + mt * 16 + g;
#pragma unroll
        for (int nt = 0; nt < 4; nt++) {
            const int cn = n0 + warp_n0 + nt * 8 + 2 * t;
            float a0 = acc[mt][nt][0], a1 = acc[mt][nt][1];
            float a2 = acc[mt][nt][2], a3 = acc[mt][nt][3];
            if (f32out) {
                float b0 = bias[cn], b1 = bias[cn + 1];
                float* Cf = (float*)C;
                *(float2*)(Cf + (size_t)rm * Dv + cn) = make_float2(a0 + b0, a1 + b1);
                *(float2*)(Cf + (size_t)(rm + 8) * Dv + cn) = make_float2(a2 + b0, a3 + b1);
            } else if (z == tz) {
                __half* Ct = (__half*)C;   // vt[d][token]
                Ct[(size_t)cn * Mv + rm]           = __float2half_rn(a0);
                Ct[(size_t)(cn + 1) * Mv + rm]     = __float2half_rn(a1);
                Ct[(size_t)cn * Mv + rm + 8]       = __float2half_rn(a2);
                Ct[(size_t)(cn + 1) * Mv + rm + 8] = __float2half_rn(a3);
            } else {
                __half2* Ch = (__half2*)C;
                Ch[((size_t)rm * Dv + cn) >> 1] = __floats2half2_rn(a0 * sc, a1 * sc);
                Ch[((size_t)(rm + 8) * Dv + cn) >> 1] = __floats2half2_rn(a2 * sc, a3 * sc);
            }
        }
    }
}

// ---------------------------------------------------------------------------
// fp16 mma flash attention, round-7:
//  - ex2.approx.f16x2 for P (halves MUFU, P born as half2)
//  - ones-column PV mma accumulates row-sum l in the tensor pipe (acc[8]),
//    exactly consistent with the fp16 P used for PV; no scalar sum pass.
// ---------------------------------------------------------------------------
#define AS 72
#define OFFK 0
#define OFFV (2 * 64 * AS)
#define OFFP (OFFV + 2 * 64 * AS)
#define OFFM_B ((OFFP + 128 * AS) * 2)
#define ATTN_SMEM (OFFM_B + 2 * 64 * 4)   // 55808 B

#define ONES2 0x3C003C00u   // half2(1.0, 1.0)

__global__ __launch_bounds__(256, 2)
void attn_h16(const __half* __restrict__ q,
              const __half* __restrict__ k,
              const __half* __restrict__ vt,
              const float* __restrict__ mask,
              __half* __restrict__ ctx) {
    extern __shared__ __half smh[];
    __half* KsB = smh + OFFK;
    __half* VsB = smh + OFFV;
    __half* Ps  = smh + OFFP;
    float* MkB  = (float*)((char*)smh + OFFM_B);

    const int tid  = threadIdx.x;
    const int wid  = tid >> 5;
    const int lane = tid & 31;
    const int g = lane >> 2;
    const int t = lane & 3;
    const int quad = lane >> 3;
    const int rb = lane & 7;
    const int q1 = quad & 1;
    const int q2 = quad >> 1;
    const int b  = blockIdx.z;
    const int h  = blockIdx.y;
    const int q0 = blockIdx.x * 128;
    const int row0 = wid * 16;

    const uint32_t ks_b = smem_u32(KsB);
    const uint32_t vs_b = smem_u32(VsB);
    const uint32_t ps_b = smem_u32(Ps);
    const uint32_t psw_b = ps_b + (uint32_t)(row0 * AS) * 2;

    auto prefetch = [&](int it) {
        const int buf = it & 1;
        const int k0 = it * 64;
        const uint32_t ks = ks_b + (uint32_t)(buf * 64 * AS) * 2;
        const uint32_t vs = vs_b + (uint32_t)(buf * 64 * AS) * 2;
        const __half* kg = k + (size_t)(b * Sv + k0) * Dv + h * DHv;
        const __half* vg = vt + (size_t)(h * DHv) * Mv + b * Sv + k0;
#pragma unroll
        for (int p = 0; p < 2; p++) {
            int idx = p * 256 + tid;
            int r = idx >> 3, c = idx & 7;
            CP16(ks + (uint32_t)(r * AS + c * 8) * 2, kg + (size_t)r * Dv + c * 8);
        }
#pragma unroll
        for (int p = 0; p < 2; p++) {
            int idx = p * 256 + tid;
            int r = idx >> 3, c = idx & 7;
            CP16(vs + (uint32_t)(r * AS + c * 8) * 2, vg + (size_t)r * Mv + c * 8);
        }
        if (tid < 16)
            CP16(smem_u32(MkB + buf * 64 + tid * 4), mask + b * Sv + k0 + tid * 4);
    };

    prefetch(0); CP_COMMIT();
    prefetch(1); CP_COMMIT();

    // Stage Q tile, extract A-fragments via ldmatrix
    {
        const __half* qg = q + (size_t)(b * Sv + q0) * Dv + h * DHv;
#pragma unroll
        for (int p = 0; p < 4; p++) {
            int idx = p * 256 + tid;
            int r = idx >> 3, c = idx & 7;
            *(uint4*)(Ps + r * AS + c * 8) = *(const uint4*)(qg + (size_t)r * Dv + c * 8);
        }
    }
    __syncthreads();

    uint32_t qf[4][4];
#pragma unroll
    for (int kk = 0; kk < 4; kk++) {
        uint32_t off = (uint32_t)((row0 + q1 * 8 + rb) * AS + kk * 16 + q2 * 8);
        ldm_x4(qf[kk], ps_b + off * 2);
    }
    __syncthreads();

    float m_lo = -1e30f, m_hi = -1e30f;
    // acc[0..7] = context columns; acc[8] = row-sum l (ones column)
    float acc[9][4];
#pragma unroll
    for (int nt = 0; nt < 9; nt++)
#pragma unroll
        for (int e = 0; e < 4; e++) acc[nt][e] = 0.f;

    __half* PsW = Ps + row0 * AS;
    const uint32_t ones_b[2] = {ONES2, ONES2};

    for (int it = 0; it < Sv / 64; it++) {
        const int buf = it & 1;
        const uint32_t ks = ks_b + (uint32_t)(buf * 64 * AS) * 2;
        const uint32_t vs = vs_b + (uint32_t)(buf * 64 * AS) * 2;
        const float* Mk = MkB + buf * 64;

        CP_WAIT1();
        __syncthreads();

        // --- S = Q @ K^T ---
        float s[8][4];
#pragma unroll
        for (int nt = 0; nt < 8; nt++)
#pragma unroll
            for (int e = 0; e < 4; e++) s[nt][e] = 0.f;

#pragma unroll
        for (int kk = 0; kk < 4; kk++) {
            uint32_t bfr[4][4];
#pragma unroll
            for (int ntp = 0; ntp < 4; ntp++) {
                uint32_t off = (uint32_t)((ntp * 16 + q2 * 8 + rb) * AS + kk * 16 + q1 * 8);
                ldm_x4(bfr[ntp], ks + off * 2);
            }
#pragma unroll
            for (int nt = 0; nt < 8; nt++)
                mma_f16(s[nt], qf[kk], &bfr[nt >> 1][(nt & 1) * 2]);
        }

        // --- mask + online max (fp32) ---
        float tmax_lo = -1e30f, tmax_hi = -1e30f;
#pragma unroll
        for (int nt = 0; nt < 8; nt++) {
            float mv0 = Mk[nt * 8 + 2 * t];
            float mv1 = Mk[nt * 8 + 2 * t + 1];
            s[nt][0] = fmaf(mv0, LOG2E, s[nt][0]);
            s[nt][1] = fmaf(mv1, LOG2E, s[nt][1]);
            s[nt][2] = fmaf(mv0, LOG2E, s[nt][2]);
            s[nt][3] = fmaf(mv1, LOG2E, s[nt][3]);
            tmax_lo = fmaxf(tmax_lo, fmaxf(s[nt][0], s[nt][1]));
            tmax_hi = fmaxf(tmax_hi, fmaxf(s[nt][2], s[nt][3]));
        }
#pragma unroll
        for (int o = 1; o < 4; o <<= 1) {
            tmax_lo = fmaxf(tmax_lo, __shfl_xor_sync(0xffffffffu, tmax_lo, o));
            tmax_hi = fmaxf(tmax_hi, __shfl_xor_sync(0xffffffffu, tmax_hi, o));
        }
        float nm_lo = fmaxf(m_lo, tmax_lo);
        float nm_hi = fmaxf(m_hi, tmax_hi);
        float cr_lo = ex2f(m_lo - nm_lo);
        float cr_hi = ex2f(m_hi - nm_hi);
        m_lo = nm_lo; m_hi = nm_hi;

        // rescale running acc (incl. ones column -> l)
#pragma unroll
        for (int nt = 0; nt < 9; nt++) {
            acc[nt][0] *= cr_lo; acc[nt][1] *= cr_lo;
            acc[nt][2] *= cr_hi; acc[nt][3] *= cr_hi;
        }

        // --- P = exp2(s - m) in half2 (one MUFU per pair), store to SMEM ---
#pragma unroll
        for (int nt = 0; nt < 8; nt++) {
            uint32_t plo = h2ex2(pack_h2(s[nt][0] - nm_lo, s[nt][1] - nm_lo));
            uint32_t phi = h2ex2(pack_h2(s[nt][2] - nm_hi, s[nt][3] - nm_hi));
            *(uint32_t*)(PsW + g * AS + nt * 8 + 2 * t) = plo;
            *(uint32_t*)(PsW + (g + 8) * AS + nt * 8 + 2 * t) = phi;
        }
        __syncwarp();

        // --- acc += P @ [V | 1] ---
#pragma unroll
        for (int kk = 0; kk < 4; kk++) {
            uint32_t af[4];
            {
                uint32_t off = (uint32_t)((q1 * 8 + rb) * AS + kk * 16 + q2 * 8);
                ldm_x4(af, psw_b + off * 2);
            }
            uint32_t bfr[4][4];
#pragma unroll
            for (int ntp = 0; ntp < 4; ntp++) {
                uint32_t off = (uint32_t)((ntp * 16 + q2 * 8 + rb) * AS + kk * 16 + q1 * 8);
                ldm_x4(bfr[ntp], vs + off * 2);
            }
#pragma unroll
            for (int nt = 0; nt < 8; nt++)
                mma_f16(acc[nt], af, &bfr[nt >> 1][(nt & 1) * 2]);
            mma_f16(acc[8], af, ones_b);   // row-sum l
        }
        __syncthreads();

        if (it + 2 < Sv / 64) prefetch(it + 2);
        CP_COMMIT();
    }

    const float inv_lo = 1.0f / acc[8][0];
    const float inv_hi = 1.0f / acc[8][2];
    __half* c0 = ctx + (size_t)(b * Sv + q0 + row0 + g) * Dv + h * DHv;
    __half* c1 = ctx + (size_t)(b * Sv + q0 + row0 + 8 + g) * Dv + h * DHv;
#pragma unroll
    for (int nt = 0; nt < 8; nt++) {
        int cn = nt * 8 + 2 * t;
        *(__half2*)(c0 + cn) = __floats2half2_rn(acc[nt][0] * inv_lo, acc[nt][1] * inv_lo);
        *(__half2*)(c1 + cn) = __floats2half2_rn(acc[nt][2] * inv_hi, acc[nt][3] * inv_hi);
    }
}

// ---------------------------------------------------------------------------
// Launch
// ---------------------------------------------------------------------------
extern "C" void kernel_launch(void* const* d_in, const int* in_sizes, int n_in,
                              void* d_out, int out_size) {
    const float* x    = (const float*)d_in[0];
    const float* mask = (const float*)d_in[1];
    const float* Wq   = (const float*)d_in[2];
    const float* Wk   = (const float*)d_in[3];
    const float* Wv   = (const float*)d_in[4];
    const float* Wo   = (const float*)d_in[5];
    const float* bo   = (const float*)d_in[6];
    float* out = (float*)d_out;

    __half *xh, *qh, *kh, *vt, *ctxh, *wqt, *wkt, *wvt, *wot;
    cudaGetSymbolAddress((void**)&xh,   g_xh);
    cudaGetSymbolAddress((void**)&qh,   g_qh);
    cudaGetSymbolAddress((void**)&kh,   g_kh);
    cudaGetSymbolAddress((void**)&vt,   g_vt);
    cudaGetSymbolAddress((void**)&ctxh, g_ctxh);
    cudaGetSymbolAddress((void**)&wqt,  g_wqt);
    cudaGetSymbolAddress((void**)&wkt,  g_wkt);
    cudaGetSymbolAddress((void**)&wvt,  g_wvt);
    cudaGetSymbolAddress((void**)&wot,  g_wot);

    conv_half<<<(Mv * Dv / 4) / 256, 256>>>(x, xh);
    transpose_w4<<<dim3(32, 32, 4), dim3(32, 8)>>>(Wq, Wk, Wv, Wo,
                                                   wqt, wkt, wvt, wot);

    cudaFuncSetAttribute(h16_gemm,
                         cudaFuncAttributeMaxDynamicSharedMemorySize, GEMM_SMEM);
    cudaFuncSetAttribute(attn_h16,
                         cudaFuncAttributeMaxDynamicSharedMemorySize, ATTN_SMEM);

    const float qscale = LOG2E / 32.0f;
    h16_gemm<<<dim3(Dv / 128, Mv / 128, 3), 256, GEMM_SMEM>>>(
        xh, wqt, wkt, wvt, qh, kh, vt, nullptr, qscale, 2, 0);

    attn_h16<<<dim3(Sv / 128, Hv, Bv), 256, ATTN_SMEM>>>(qh, kh, vt, mask, ctxh);

    h16_gemm<<<dim3(Dv / 128, Mv / 128, 1), 256, GEMM_SMEM>>>(
        ctxh, wot, wot, wot, out, out, out, bo, 1.0f, -1, 1);
}

// round 8
// speedup vs baseline: 8.5826x; 1.0271x over previous
#include <cuda_runtime.h>
#include <cuda_fp16.h>
#include <cstdint>
#include <math.h>

// Problem constants
#define Bv  2
#define Sv  2048
#define Dv  1024
#define Hv  16
#define DHv 64
#define Mv  (Bv * Sv)   // 4096

#define LOG2E 1.4426950408889634f

// Scratch (__device__ globals)
__device__ __half g_xh[Mv * Dv];
__device__ __half g_qh[Mv * Dv];
__device__ __half g_kh[Mv * Dv];
__device__ __half g_vt[Dv * Mv];      // V transposed: [d][token]
__device__ __half g_ctxh[Mv * Dv];
__device__ __half g_wqt[Dv * Dv];     // W transposed fp16: [n][k]
__device__ __half g_wkt[Dv * Dv];
__device__ __half g_wvt[Dv * Dv];
__device__ __half g_wot[Dv * Dv];

// ---------------------------------------------------------------------------
// Helpers (arch-generic PTX: mma.sync f16 + cp.async + ldmatrix)
// ---------------------------------------------------------------------------
__device__ __forceinline__ uint32_t smem_u32(const void* p) {
    uint32_t a;
    asm("{ .reg .u64 t; cvta.to.shared.u64 t, %1; cvt.u32.u64 %0, t; }" : "=r"(a) : "l"(p));
    return a;
}
#define CP16(dst, src) \
    asm volatile("cp.async.cg.shared.global [%0], [%1], 16;" :: "r"(dst), "l"(src))
#define CP_COMMIT() asm volatile("cp.async.commit_group;" ::: "memory")
#define CP_WAIT1()  asm volatile("cp.async.wait_group 1;" ::: "memory")
#define CP_WAIT2()  asm volatile("cp.async.wait_group 2;" ::: "memory")

__device__ __forceinline__ float ex2f(float x) {
    float r;
    asm("ex2.approx.f32 %0, %1;" : "=f"(r) : "f"(x));
    return r;
}
// packed half2 exp2 (one MUFU instruction for 2 values)
__device__ __forceinline__ uint32_t h2ex2(uint32_t x) {
    uint32_t r;
    asm("ex2.approx.f16x2 %0, %1;" : "=r"(r) : "r"(x));
    return r;
}
__device__ __forceinline__ uint32_t pack_h2(float lo, float hi) {
    uint32_t r;
    asm("cvt.rn.f16x2.f32 %0, %2, %1;" : "=r"(r) : "f"(lo), "f"(hi));
    return r;
}
__device__ __forceinline__ void mma_f16(float c[4], const uint32_t a[4],
                                        const uint32_t b[2]) {
    asm volatile(
        "mma.sync.aligned.m16n8k16.row.col.f32.f16.f16.f32 "
        "{%0,%1,%2,%3}, {%4,%5,%6,%7}, {%8,%9}, {%0,%1,%2,%3};"
        : "+f"(c[0]), "+f"(c[1]), "+f"(c[2]), "+f"(c[3])
        : "r"(a[0]), "r"(a[1]), "r"(a[2]), "r"(a[3]), "r"(b[0]), "r"(b[1]));
}
__device__ __forceinline__ void ldm_x4(uint32_t r[4], uint32_t addr) {
    asm volatile(
        "ldmatrix.sync.aligned.m8n8.x4.shared.b16 {%0,%1,%2,%3}, [%4];"
        : "=r"(r[0]), "=r"(r[1]), "=r"(r[2]), "=r"(r[3]) : "r"(addr));
}

// ---------------------------------------------------------------------------
// Preprocess kernels
// ---------------------------------------------------------------------------
__global__ void conv_half(const float* __restrict__ in, __half* __restrict__ out) {
    int i = blockIdx.x * blockDim.x + threadIdx.x;   // one float4
    float4 v = ((const float4*)in)[i];
    __half2* o = (__half2*)out + i * 2;
    o[0] = __floats2half2_rn(v.x, v.y);
    o[1] = __floats2half2_rn(v.z, v.w);
}

// 4 weight transposes in one launch (z selects). fp32 [k][n] -> fp16 [n][k].
__global__ void transpose_w4(const float* __restrict__ w0, const float* __restrict__ w1,
                             const float* __restrict__ w2, const float* __restrict__ w3,
                             __half* __restrict__ o0, __half* __restrict__ o1,
                             __half* __restrict__ o2, __half* __restrict__ o3) {
    const float* in  = (blockIdx.z == 0) ? w0 : (blockIdx.z == 1) ? w1
                     : (blockIdx.z == 2) ? w2 : w3;
    __half* out = (blockIdx.z == 0) ? o0 : (blockIdx.z == 1) ? o1
                : (blockIdx.z == 2) ? o2 : o3;
    __shared__ __half t[32][33];
    int x = blockIdx.x * 32 + threadIdx.x;
    int y0 = blockIdx.y * 32;
#pragma unroll
    for (int i = 0; i < 32; i += 8)
        t[threadIdx.y + i][threadIdx.x] =
            __float2half_rn(in[(size_t)(y0 + threadIdx.y + i) * Dv + x]);
    __syncthreads();
    int ox = blockIdx.y * 32 + threadIdx.x;
    int oy0 = blockIdx.x * 32;
#pragma unroll
    for (int i = 0; i < 32; i += 8)
        out[(size_t)(oy0 + threadIdx.y + i) * Dv + ox] = t[threadIdx.x][threadIdx.y + i];
}

// ---------------------------------------------------------------------------
// fp16 mma GEMM (round-6, unchanged): CTA 128x128, BK=64, 3-stage cp.async,
// XOR-swizzled rows, ldmatrix fragments.
// ---------------------------------------------------------------------------
#define SWZ(r, c) (((r) << 6) + (((c) ^ ((r) & 7)) << 3))
#define STAGE_H (2 * 128 * 64)
#define GEMM_SMEM (3 * STAGE_H * 2)            // 98304 B

__global__ __launch_bounds__(256, 2)
void h16_gemm(const __half* __restrict__ A,
              const __half* __restrict__ w0, const __half* __restrict__ w1,
              const __half* __restrict__ w2,
              void* __restrict__ c0, void* __restrict__ c1, void* __restrict__ c2,
              const float* __restrict__ bias, float qscale, int tz, int f32out) {
    extern __shared__ __half smh[];

    const int tid  = threadIdx.x;
    const int wid  = tid >> 5;
    const int lane = tid & 31;
    const int g = lane >> 2;
    const int t = lane & 3;
    const int quad = lane >> 3;
    const int rb = lane & 7;
    const int q1 = quad & 1;
    const int q2 = quad >> 1;
    const int z = blockIdx.z;

    const __half* W = (z == 0) ? w0 : (z == 1) ? w1 : w2;
    void* C = (z == 0) ? c0 : (z == 1) ? c1 : c2;

    const int n0 = blockIdx.x * 128;
    const int m0 = blockIdx.y * 128;
    const int warp_m0 = (wid >> 2) * 64;
    const int warp_n0 = (wid & 3) * 32;

    const uint32_t smem_b = smem_u32(smh);

    float acc[4][4][4];
#pragma unroll
    for (int mt = 0; mt < 4; mt++)
#pragma unroll
        for (int nt = 0; nt < 4; nt++)
#pragma unroll
            for (int e = 0; e < 4; e++) acc[mt][nt][e] = 0.f;

    auto prefetch = [&](int chunk, int buf) {
        const int k0 = chunk * 64;
        const uint32_t as = smem_b + buf * STAGE_H * 2;
        const uint32_t bs = as + 128 * 64 * 2;
        const __half* Ag = A + (size_t)m0 * Dv + k0;
        const __half* Bg = W + (size_t)n0 * Dv + k0;
#pragma unroll
        for (int it = 0; it < 4; it++) {
            int idx = it * 256 + tid;
            int r = idx >> 3, c = idx & 7;
            CP16(as + SWZ(r, c) * 2, Ag + (size_t)r * Dv + c * 8);
        }
#pragma unroll
        for (int it = 0; it < 4; it++) {
            int idx = it * 256 + tid;
            int r = idx >> 3, c = idx & 7;
            CP16(bs + SWZ(r, c) * 2, Bg + (size_t)r * Dv + c * 8);
        }
    };

    prefetch(0, 0); CP_COMMIT();
    prefetch(1, 1); CP_COMMIT();
    prefetch(2, 2); CP_COMMIT();

    for (int chunk = 0; chunk < Dv / 64; chunk++) {
        const int buf = (chunk % 3);
        CP_WAIT2();
        __syncthreads();

        const uint32_t as = smem_b + buf * STAGE_H * 2;
        const uint32_t bs = as + 128 * 64 * 2;

#pragma unroll
        for (int kk = 0; kk < 4; kk++) {
            uint32_t af[4][4];
#pragma unroll
            for (int mt = 0; mt < 4; mt++) {
                int row = warp_m0 + mt * 16 + q1 * 8 + rb;
                uint32_t off = (uint32_t)((row << 6) + (((kk * 2 + q2) ^ rb) << 3));
                ldm_x4(af[mt], as + off * 2);
            }
            uint32_t bfr[2][4];
#pragma unroll
            for (int ntp = 0; ntp < 2; ntp++) {
                int row = warp_n0 + ntp * 16 + q2 * 8 + rb;
                uint32_t off = (uint32_t)((row << 6) + (((kk * 2 + q1) ^ rb) << 3));
                ldm_x4(bfr[ntp], bs + off * 2);
            }
#pragma unroll
            for (int mt = 0; mt < 4; mt++)
#pragma unroll
                for (int nt = 0; nt < 4; nt++)
                    mma_f16(acc[mt][nt], af[mt], &bfr[nt >> 1][(nt & 1) * 2]);
        }
        __syncthreads();

        if (chunk + 3 < Dv / 64) prefetch(chunk + 3, buf);
        CP_COMMIT();
    }

    const float sc = (z == 0) ? qscale : 1.0f;
#pragma unroll
    for (int mt = 0; mt < 4; mt++) {
        const int rm = m0 + warp_m0 + mt * 16 + g;
#pragma unroll
        for (int nt = 0; nt < 4; nt++) {
            const int cn = n0 + warp_n0 + nt * 8 + 2 * t;
            float a0 = acc[mt][nt][0], a1 = acc[mt][nt][1];
            float a2 = acc[mt][nt][2], a3 = acc[mt][nt][3];
            if (f32out) {
                float b0 = bias[cn], b1 = bias[cn + 1];
                float* Cf = (float*)C;
                *(float2*)(Cf + (size_t)rm * Dv + cn) = make_float2(a0 + b0, a1 + b1);
                *(float2*)(Cf + (size_t)(rm + 8) * Dv + cn) = make_float2(a2 + b0, a3 + b1);
            } else if (z == tz) {
                __half* Ct = (__half*)C;   // vt[d][token]
                Ct[(size_t)cn * Mv + rm]           = __float2half_rn(a0);
                Ct[(size_t)(cn + 1) * Mv + rm]     = __float2half_rn(a1);
                Ct[(size_t)cn * Mv + rm + 8]       = __float2half_rn(a2);
                Ct[(size_t)(cn + 1) * Mv + rm + 8] = __float2half_rn(a3);
            } else {
                __half2* Ch = (__half2*)C;
                Ch[((size_t)rm * Dv + cn) >> 1] = __floats2half2_rn(a0 * sc, a1 * sc);
                Ch[((size_t)(rm + 8) * Dv + cn) >> 1] = __floats2half2_rn(a2 * sc, a3 * sc);
            }
        }
    }
}

// ---------------------------------------------------------------------------
// fp16 mma flash attention, round-8: FA2 register-resident P.
// The h2ex2 outputs ARE the PV A-fragments (C-fragment layout == A-fragment
// layout): pfrag[nt][0] = {P[g][2t],P[g][2t+1]}, pfrag[nt][1] = rows g+8.
// PV kk-chunk af = {pfrag[2kk][0], pfrag[2kk][1], pfrag[2kk+1][0],
// pfrag[2kk+1][1]}. No P SMEM store, no ldmatrix, no syncwarp.
// ---------------------------------------------------------------------------
#define AS 72
#define OFFK 0
#define OFFV (2 * 64 * AS)
#define OFFQ (OFFV + 2 * 64 * AS)          // Q staging only
#define OFFM_B ((OFFQ + 128 * AS) * 2)
#define ATTN_SMEM (OFFM_B + 2 * 64 * 4)    // 55808 B

#define ONES2 0x3C003C00u   // half2(1.0, 1.0)

__global__ __launch_bounds__(256, 2)
void attn_h16(const __half* __restrict__ q,
              const __half* __restrict__ k,
              const __half* __restrict__ vt,
              const float* __restrict__ mask,
              __half* __restrict__ ctx) {
    extern __shared__ __half smh[];
    __half* KsB = smh + OFFK;
    __half* VsB = smh + OFFV;
    __half* Qs  = smh + OFFQ;
    float* MkB  = (float*)((char*)smh + OFFM_B);

    const int tid  = threadIdx.x;
    const int wid  = tid >> 5;
    const int lane = tid & 31;
    const int g = lane >> 2;
    const int t = lane & 3;
    const int quad = lane >> 3;
    const int rb = lane & 7;
    const int q1 = quad & 1;
    const int q2 = quad >> 1;
    const int b  = blockIdx.z;
    const int h  = blockIdx.y;
    const int q0 = blockIdx.x * 128;
    const int row0 = wid * 16;

    const uint32_t ks_b = smem_u32(KsB);
    const uint32_t vs_b = smem_u32(VsB);
    const uint32_t qs_b = smem_u32(Qs);

    auto prefetch = [&](int it) {
        const int buf = it & 1;
        const int k0 = it * 64;
        const uint32_t ks = ks_b + (uint32_t)(buf * 64 * AS) * 2;
        const uint32_t vs = vs_b + (uint32_t)(buf * 64 * AS) * 2;
        const __half* kg = k + (size_t)(b * Sv + k0) * Dv + h * DHv;
        const __half* vg = vt + (size_t)(h * DHv) * Mv + b * Sv + k0;
#pragma unroll
        for (int p = 0; p < 2; p++) {
            int idx = p * 256 + tid;
            int r = idx >> 3, c = idx & 7;
            CP16(ks + (uint32_t)(r * AS + c * 8) * 2, kg + (size_t)r * Dv + c * 8);
        }
#pragma unroll
        for (int p = 0; p < 2; p++) {
            int idx = p * 256 + tid;
            int r = idx >> 3, c = idx & 7;
            CP16(vs + (uint32_t)(r * AS + c * 8) * 2, vg + (size_t)r * Mv + c * 8);
        }
        if (tid < 16)
            CP16(smem_u32(MkB + buf * 64 + tid * 4), mask + b * Sv + k0 + tid * 4);
    };

    prefetch(0); CP_COMMIT();
    prefetch(1); CP_COMMIT();

    // Stage Q tile, extract A-fragments via ldmatrix
    {
        const __half* qg = q + (size_t)(b * Sv + q0) * Dv + h * DHv;
#pragma unroll
        for (int p = 0; p < 4; p++) {
            int idx = p * 256 + tid;
            int r = idx >> 3, c = idx & 7;
            *(uint4*)(Qs + r * AS + c * 8) = *(const uint4*)(qg + (size_t)r * Dv + c * 8);
        }
    }
    __syncthreads();

    uint32_t qf[4][4];
#pragma unroll
    for (int kk = 0; kk < 4; kk++) {
        uint32_t off = (uint32_t)((row0 + q1 * 8 + rb) * AS + kk * 16 + q2 * 8);
        ldm_x4(qf[kk], qs_b + off * 2);
    }
    __syncthreads();

    float m_lo = -1e30f, m_hi = -1e30f;
    // acc[0..7] = context columns; acc[8] = row-sum l (ones column)
    float acc[9][4];
#pragma unroll
    for (int nt = 0; nt < 9; nt++)
#pragma unroll
        for (int e = 0; e < 4; e++) acc[nt][e] = 0.f;

    const uint32_t ones_b[2] = {ONES2, ONES2};

    for (int it = 0; it < Sv / 64; it++) {
        const int buf = it & 1;
        const uint32_t ks = ks_b + (uint32_t)(buf * 64 * AS) * 2;
        const uint32_t vs = vs_b + (uint32_t)(buf * 64 * AS) * 2;
        const float* Mk = MkB + buf * 64;

        CP_WAIT1();
        __syncthreads();

        // --- S = Q @ K^T ---
        float s[8][4];
#pragma unroll
        for (int nt = 0; nt < 8; nt++)
#pragma unroll
            for (int e = 0; e < 4; e++) s[nt][e] = 0.f;

#pragma unroll
        for (int kk = 0; kk < 4; kk++) {
            uint32_t bfr[4][4];
#pragma unroll
            for (int ntp = 0; ntp < 4; ntp++) {
                uint32_t off = (uint32_t)((ntp * 16 + q2 * 8 + rb) * AS + kk * 16 + q1 * 8);
                ldm_x4(bfr[ntp], ks + off * 2);
            }
#pragma unroll
            for (int nt = 0; nt < 8; nt++)
                mma_f16(s[nt], qf[kk], &bfr[nt >> 1][(nt & 1) * 2]);
        }

        // --- mask + online max (fp32) ---
        float tmax_lo = -1e30f, tmax_hi = -1e30f;
#pragma unroll
        for (int nt = 0; nt < 8; nt++) {
            float mv0 = Mk[nt * 8 + 2 * t];
            float mv1 = Mk[nt * 8 + 2 * t + 1];
            s[nt][0] = fmaf(mv0, LOG2E, s[nt][0]);
            s[nt][1] = fmaf(mv1, LOG2E, s[nt][1]);
            s[nt][2] = fmaf(mv0, LOG2E, s[nt][2]);
            s[nt][3] = fmaf(mv1, LOG2E, s[nt][3]);
            tmax_lo = fmaxf(tmax_lo, fmaxf(s[nt][0], s[nt][1]));
            tmax_hi = fmaxf(tmax_hi, fmaxf(s[nt][2], s[nt][3]));
        }
#pragma unroll
        for (int o = 1; o < 4; o <<= 1) {
            tmax_lo = fmaxf(tmax_lo, __shfl_xor_sync(0xffffffffu, tmax_lo, o));
            tmax_hi = fmaxf(tmax_hi, __shfl_xor_sync(0xffffffffu, tmax_hi, o));
        }
        float nm_lo = fmaxf(m_lo, tmax_lo);
        float nm_hi = fmaxf(m_hi, tmax_hi);
        float cr_lo = ex2f(m_lo - nm_lo);
        float cr_hi = ex2f(m_hi - nm_hi);
        m_lo = nm_lo; m_hi = nm_hi;

        // rescale running acc (incl. ones column -> l)
#pragma unroll
        for (int nt = 0; nt < 9; nt++) {
            acc[nt][0] *= cr_lo; acc[nt][1] *= cr_lo;
            acc[nt][2] *= cr_hi; acc[nt][3] *= cr_hi;
        }

        // --- P = exp2(s - m): register-resident PV A-fragments ---
        uint32_t pfrag[8][2];
#pragma unroll
        for (int nt = 0; nt < 8; nt++) {
            pfrag[nt][0] = h2ex2(pack_h2(s[nt][0] - nm_lo, s[nt][1] - nm_lo));
            pfrag[nt][1] = h2ex2(pack_h2(s[nt][2] - nm_hi, s[nt][3] - nm_hi));
        }

        // --- acc += P @ [V | 1] (P straight from registers) ---
#pragma unroll
        for (int kk = 0; kk < 4; kk++) {
            uint32_t af[4] = {pfrag[2 * kk][0], pfrag[2 * kk][1],
                              pfrag[2 * kk + 1][0], pfrag[2 * kk + 1][1]};
            uint32_t bfr[4][4];
#pragma unroll
            for (int ntp = 0; ntp < 4; ntp++) {
                uint32_t off = (uint32_t)((ntp * 16 + q2 * 8 + rb) * AS + kk * 16 + q1 * 8);
                ldm_x4(bfr[ntp], vs + off * 2);
            }
#pragma unroll
            for (int nt = 0; nt < 8; nt++)
                mma_f16(acc[nt], af, &bfr[nt >> 1][(nt & 1) * 2]);
            mma_f16(acc[8], af, ones_b);   // row-sum l
        }
        __syncthreads();

        if (it + 2 < Sv / 64) prefetch(it + 2);
        CP_COMMIT();
    }

    const float inv_lo = 1.0f / acc[8][0];
    const float inv_hi = 1.0f / acc[8][2];
    __half* c0 = ctx + (size_t)(b * Sv + q0 + row0 + g) * Dv + h * DHv;
    __half* c1 = ctx + (size_t)(b * Sv + q0 + row0 + 8 + g) * Dv + h * DHv;
#pragma unroll
    for (int nt = 0; nt < 8; nt++) {
        int cn = nt * 8 + 2 * t;
        *(__half2*)(c0 + cn) = __floats2half2_rn(acc[nt][0] * inv_lo, acc[nt][1] * inv_lo);
        *(__half2*)(c1 + cn) = __floats2half2_rn(acc[nt][2] * inv_hi, acc[nt][3] * inv_hi);
    }
}

// ---------------------------------------------------------------------------
// Launch
// ---------------------------------------------------------------------------
extern "C" void kernel_launch(void* const* d_in, const int* in_sizes, int n_in,
                              void* d_out, int out_size) {
    const float* x    = (const float*)d_in[0];
    const float* mask = (const float*)d_in[1];
    const float* Wq   = (const float*)d_in[2];
    const float* Wk   = (const float*)d_in[3];
    const float* Wv   = (const float*)d_in[4];
    const float* Wo   = (const float*)d_in[5];
    const float* bo   = (const float*)d_in[6];
    float* out = (float*)d_out;

    __half *xh, *qh, *kh, *vt, *ctxh, *wqt, *wkt, *wvt, *wot;
    cudaGetSymbolAddress((void**)&xh,   g_xh);
    cudaGetSymbolAddress((void**)&qh,   g_qh);
    cudaGetSymbolAddress((void**)&kh,   g_kh);
    cudaGetSymbolAddress((void**)&vt,   g_vt);
    cudaGetSymbolAddress((void**)&ctxh, g_ctxh);
    cudaGetSymbolAddress((void**)&wqt,  g_wqt);
    cudaGetSymbolAddress((void**)&wkt,  g_wkt);
    cudaGetSymbolAddress((void**)&wvt,  g_wvt);
    cudaGetSymbolAddress((void**)&wot,  g_wot);

    conv_half<<<(Mv * Dv / 4) / 256, 256>>>(x, xh);
    transpose_w4<<<dim3(32, 32, 4), dim3(32, 8)>>>(Wq, Wk, Wv, Wo,
                                                   wqt, wkt, wvt, wot);

    cudaFuncSetAttribute(h16_gemm,
                         cudaFuncAttributeMaxDynamicSharedMemorySize, GEMM_SMEM);
    cudaFuncSetAttribute(attn_h16,
                         cudaFuncAttributeMaxDynamicSharedMemorySize, ATTN_SMEM);

    const float qscale = LOG2E / 32.0f;
    h16_gemm<<<dim3(Dv / 128, Mv / 128, 3), 256, GEMM_SMEM>>>(
        xh, wqt, wkt, wvt, qh, kh, vt, nullptr, qscale, 2, 0);

    attn_h16<<<dim3(Sv / 128, Hv, Bv), 256, ATTN_SMEM>>>(qh, kh, vt, mask, ctxh);

    h16_gemm<<<dim3(Dv / 128, Mv / 128, 1), 256, GEMM_SMEM>>>(
        ctxh, wot, wot, wot, out, out, out, bo, 1.0f, -1, 1);
}